// round 1
// baseline (speedup 1.0000x reference)
#include <cuda_runtime.h>
#include <math.h>
#include <stdint.h>

// ---------------------------------------------------------------------------
// CausalTransformer: B=2, T=5120, FEAT=256, TIN=5 -> S=1024 patches
// HDIM=1024, N_HEADS=16, HEAD_DIM=64, N_LAYERS=8, FF_DIM=4096, NUM_CLASSES=100
// ---------------------------------------------------------------------------

#define SLEN   1024
#define NB     2
#define BS     2048          // NB * SLEN rows
#define HDIM   1024
#define INDIM  1280          // TIN * FEAT
#define QKVD   3072
#define FFD    4096
#define NH     16
#define HD     64
#define NC     100
#define NLAY   8
#define LREL   257

// ------------------------- scratch (device globals) ------------------------
__device__ float g_ln[(size_t)BS * INDIM];
__device__ float g_z[(size_t)BS * HDIM];
__device__ float g_qkv[(size_t)BS * QKVD];
__device__ float g_ff[(size_t)BS * FFD];
__device__ float g_o[(size_t)BS * HDIM];
__device__ float g_scores[(size_t)NB * NH * SLEN * SLEN];   // 128 MB

// ------------------------------- LayerNorm ---------------------------------
__global__ void ln_kernel(const float* __restrict__ in, float* __restrict__ out,
                          const float* __restrict__ g, const float* __restrict__ b,
                          int n, float eps)
{
    int row = blockIdx.x;
    const float* p = in + (size_t)row * n;
    float* o = out + (size_t)row * n;
    int t = threadIdx.x;

    float s = 0.f, ss = 0.f;
    for (int i = t; i < n; i += blockDim.x) {
        float v = p[i];
        s += v; ss += v * v;
    }
    __shared__ float r1[256], r2[256];
    r1[t] = s; r2[t] = ss;
    __syncthreads();
    for (int st = 128; st > 0; st >>= 1) {
        if (t < st) { r1[t] += r1[t + st]; r2[t] += r2[t + st]; }
        __syncthreads();
    }
    float mean = r1[0] / n;
    float var  = r2[0] / n - mean * mean;
    float inv  = rsqrtf(var + eps);
    for (int i = t; i < n; i += blockDim.x)
        o[i] = (p[i] - mean) * inv * g[i] + b[i];
}

// --------------------- generic GEMM: C = act(A W^T + b) + res ---------------
// A: [M,K] row-major, W: [N,K] row-major, bias: [N], res: [M,N] or null
// act: 0 = none, 1 = exact gelu
// Tile 128x128, BK=8, 256 threads, per-thread 8x8.
__global__ void gemm128(const float* __restrict__ A, const float* __restrict__ W,
                        const float* __restrict__ bias, const float* __restrict__ res,
                        float* __restrict__ C, int M, int N, int K, int act)
{
    __shared__ float As[8][128];
    __shared__ float Ws[8][128];

    int t  = threadIdx.x;
    int m0 = blockIdx.y * 128;
    int n0 = blockIdx.x * 128;
    int lr = t >> 1;             // 0..127
    int lc = (t & 1) * 4;        // 0 or 4
    int ty = t >> 4;             // 0..15
    int tx = t & 15;             // 0..15

    float acc[8][8];
#pragma unroll
    for (int i = 0; i < 8; i++)
#pragma unroll
        for (int j = 0; j < 8; j++) acc[i][j] = 0.f;

    for (int k0 = 0; k0 < K; k0 += 8) {
        float4 av = make_float4(0.f, 0.f, 0.f, 0.f);
        int am = m0 + lr;
        if (am < M) av = *(const float4*)(A + (size_t)am * K + k0 + lc);
        As[lc + 0][lr] = av.x; As[lc + 1][lr] = av.y;
        As[lc + 2][lr] = av.z; As[lc + 3][lr] = av.w;

        float4 wv = make_float4(0.f, 0.f, 0.f, 0.f);
        int wn = n0 + lr;
        if (wn < N) wv = *(const float4*)(W + (size_t)wn * K + k0 + lc);
        Ws[lc + 0][lr] = wv.x; Ws[lc + 1][lr] = wv.y;
        Ws[lc + 2][lr] = wv.z; Ws[lc + 3][lr] = wv.w;
        __syncthreads();

#pragma unroll
        for (int k = 0; k < 8; k++) {
            float a[8], w[8];
            *(float4*)&a[0] = *(const float4*)&As[k][ty * 8];
            *(float4*)&a[4] = *(const float4*)&As[k][ty * 8 + 4];
            *(float4*)&w[0] = *(const float4*)&Ws[k][tx * 8];
            *(float4*)&w[4] = *(const float4*)&Ws[k][tx * 8 + 4];
#pragma unroll
            for (int i = 0; i < 8; i++)
#pragma unroll
                for (int j = 0; j < 8; j++)
                    acc[i][j] = fmaf(a[i], w[j], acc[i][j]);
        }
        __syncthreads();
    }

#pragma unroll
    for (int i = 0; i < 8; i++) {
        int m = m0 + ty * 8 + i;
        if (m >= M) continue;
#pragma unroll
        for (int j = 0; j < 8; j++) {
            int n = n0 + tx * 8 + j;
            if (n >= N) continue;
            float v = acc[i][j] + bias[n];
            if (act == 1)
                v = 0.5f * v * (1.0f + erff(v * 0.70710678118654752f));
            if (res) v += res[(size_t)m * N + n];
            C[(size_t)m * N + n] = v;
        }
    }
}

// ----------------------------- attention scores -----------------------------
// scores[bh, q, k] = 0.125 * q.k + rel_bias + causal ;  skip fully-masked tiles
__global__ void scores_kernel(const float* __restrict__ qkv,
                              const float* __restrict__ rel,
                              float* __restrict__ scores)
{
    int bh = blockIdx.z, b = bh >> 4, h = bh & 15;
    int q0 = blockIdx.y * 64, k0 = blockIdx.x * 64;
    if (k0 > q0 + 63) return;      // fully above diagonal

    __shared__ float Qs[16][64];
    __shared__ float Ks[16][64];
    int t  = threadIdx.x;
    int lr = t >> 2;           // 0..63
    int lc = (t & 3) * 4;      // 0..12
    int ty = t >> 4, tx = t & 15;

    float acc[4][4];
#pragma unroll
    for (int i = 0; i < 4; i++)
#pragma unroll
        for (int j = 0; j < 4; j++) acc[i][j] = 0.f;

    const float* qbase = qkv + (size_t)(b * SLEN + q0 + lr) * QKVD + h * HD;
    const float* kbase = qkv + (size_t)(b * SLEN + k0 + lr) * QKVD + HDIM + h * HD;

    for (int kk = 0; kk < HD; kk += 16) {
        float4 qv = *(const float4*)(qbase + kk + lc);
        float4 kv = *(const float4*)(kbase + kk + lc);
        Qs[lc + 0][lr] = qv.x; Qs[lc + 1][lr] = qv.y;
        Qs[lc + 2][lr] = qv.z; Qs[lc + 3][lr] = qv.w;
        Ks[lc + 0][lr] = kv.x; Ks[lc + 1][lr] = kv.y;
        Ks[lc + 2][lr] = kv.z; Ks[lc + 3][lr] = kv.w;
        __syncthreads();
#pragma unroll
        for (int k = 0; k < 16; k++) {
            float a[4], w[4];
            *(float4*)a = *(const float4*)&Qs[k][ty * 4];
            *(float4*)w = *(const float4*)&Ks[k][tx * 4];
#pragma unroll
            for (int i = 0; i < 4; i++)
#pragma unroll
                for (int j = 0; j < 4; j++)
                    acc[i][j] = fmaf(a[i], w[j], acc[i][j]);
        }
        __syncthreads();
    }

    float* srow = scores + (size_t)bh * SLEN * SLEN;
#pragma unroll
    for (int i = 0; i < 4; i++) {
        int q = q0 + ty * 4 + i;
#pragma unroll
        for (int j = 0; j < 4; j++) {
            int k = k0 + tx * 4 + j;
            int r = k - q;
            r = min(max(r, -128), 128) + 128;
            float v = acc[i][j] * 0.125f + rel[h * LREL + r];
            if (k > q) v = -1e9f;
            srow[(size_t)q * SLEN + k] = v;
        }
    }
}

// ------------------------------- softmax (causal) ---------------------------
__global__ void softmax_kernel(float* __restrict__ scores)
{
    int q = blockIdx.x, bh = blockIdx.y;
    float* row = scores + (size_t)bh * SLEN * SLEN + (size_t)q * SLEN;
    int n = q + 1;
    int t = threadIdx.x;
    __shared__ float red[256];

    float m = -1e30f;
    for (int i = t; i < n; i += 256) m = fmaxf(m, row[i]);
    red[t] = m; __syncthreads();
    for (int st = 128; st > 0; st >>= 1) {
        if (t < st) red[t] = fmaxf(red[t], red[t + st]);
        __syncthreads();
    }
    m = red[0];
    __syncthreads();

    float s = 0.f;
    for (int i = t; i < n; i += 256) {
        float e = __expf(row[i] - m);
        row[i] = e;
        s += e;
    }
    red[t] = s; __syncthreads();
    for (int st = 128; st > 0; st >>= 1) {
        if (t < st) red[t] += red[t + st];
        __syncthreads();
    }
    float inv = 1.0f / red[0];
    for (int i = t; i < n; i += 256) row[i] *= inv;
}

// ------------------------------ attn @ V ------------------------------------
// o[b, q, h*64 + d] = sum_{k<=q} P[bh,q,k] * V[b,k,h,d]
__global__ void av_kernel(const float* __restrict__ scores,
                          const float* __restrict__ qkv,
                          float* __restrict__ o)
{
    int bh = blockIdx.y, b = bh >> 4, h = bh & 15;
    int q0 = blockIdx.x * 64;

    __shared__ float Ps[32][64];
    __shared__ float Vs[32][64];
    int t  = threadIdx.x;
    int ty = t >> 4, tx = t & 15;
    int pr = t >> 2;            // 0..63 (q)
    int pc = (t & 3) * 8;       // 0..24 (k base)
    int vr = t >> 3;            // 0..31 (k)
    int vc = (t & 7) * 8;       // 0..56 (d base)

    float acc[4][4];
#pragma unroll
    for (int i = 0; i < 4; i++)
#pragma unroll
        for (int j = 0; j < 4; j++) acc[i][j] = 0.f;

    const float* srow = scores + (size_t)bh * SLEN * SLEN;

    for (int kk0 = 0; kk0 < q0 + 64; kk0 += 32) {
        int qg = q0 + pr;
#pragma unroll
        for (int i = 0; i < 8; i += 4) {
            float4 pv = *(const float4*)(srow + (size_t)qg * SLEN + kk0 + pc + i);
            int kb = kk0 + pc + i;
            Ps[pc + i + 0][pr] = (kb + 0 <= qg) ? pv.x : 0.f;
            Ps[pc + i + 1][pr] = (kb + 1 <= qg) ? pv.y : 0.f;
            Ps[pc + i + 2][pr] = (kb + 2 <= qg) ? pv.z : 0.f;
            Ps[pc + i + 3][pr] = (kb + 3 <= qg) ? pv.w : 0.f;
        }
        const float* vbase = qkv + (size_t)(b * SLEN + kk0 + vr) * QKVD
                             + 2 * HDIM + h * HD + vc;
        float4 v0 = *(const float4*)(vbase);
        float4 v1 = *(const float4*)(vbase + 4);
        Vs[vr][vc + 0] = v0.x; Vs[vr][vc + 1] = v0.y;
        Vs[vr][vc + 2] = v0.z; Vs[vr][vc + 3] = v0.w;
        Vs[vr][vc + 4] = v1.x; Vs[vr][vc + 5] = v1.y;
        Vs[vr][vc + 6] = v1.z; Vs[vr][vc + 7] = v1.w;
        __syncthreads();

#pragma unroll
        for (int k = 0; k < 32; k++) {
            float a[4], w[4];
            *(float4*)a = *(const float4*)&Ps[k][ty * 4];
            *(float4*)w = *(const float4*)&Vs[k][tx * 4];
#pragma unroll
            for (int i = 0; i < 4; i++)
#pragma unroll
                for (int j = 0; j < 4; j++)
                    acc[i][j] = fmaf(a[i], w[j], acc[i][j]);
        }
        __syncthreads();
    }

#pragma unroll
    for (int i = 0; i < 4; i++)
#pragma unroll
        for (int j = 0; j < 4; j++)
            o[(size_t)(b * SLEN + q0 + ty * 4 + i) * HDIM + h * HD + tx * 4 + j]
                = acc[i][j];
}

// ------------------------------- launcher -----------------------------------
extern "C" void kernel_launch(void* const* d_in, const int* in_sizes, int n_in,
                              void* d_out, int out_size)
{
    const float* x        = (const float*)d_in[0];
    const float* pe_ln1_g = (const float*)d_in[1];
    const float* pe_ln1_b = (const float*)d_in[2];
    const float* pe_w     = (const float*)d_in[3];
    const float* pe_b     = (const float*)d_in[4];
    const float* pe_ln2_g = (const float*)d_in[5];
    const float* pe_ln2_b = (const float*)d_in[6];
    const float* lnA_g    = (const float*)d_in[7];
    const float* lnA_b    = (const float*)d_in[8];
    const float* qkv_w    = (const float*)d_in[9];
    const float* qkv_b    = (const float*)d_in[10];
    const float* out_w    = (const float*)d_in[11];
    const float* out_b    = (const float*)d_in[12];
    const float* lnF_g    = (const float*)d_in[13];
    const float* lnF_b    = (const float*)d_in[14];
    const float* fc1_w    = (const float*)d_in[15];
    const float* fc1_b    = (const float*)d_in[16];
    const float* fc2_w    = (const float*)d_in[17];
    const float* fc2_b    = (const float*)d_in[18];
    const float* relt     = (const float*)d_in[19];
    const float* final_g  = (const float*)d_in[20];
    const float* final_b  = (const float*)d_in[21];
    const float* head_w   = (const float*)d_in[22];
    const float* head_b   = (const float*)d_in[23];
    float* out = (float*)d_out;

    float *ln, *z, *qkv, *ff, *o, *sc;
    cudaGetSymbolAddress((void**)&ln,  g_ln);
    cudaGetSymbolAddress((void**)&z,   g_z);
    cudaGetSymbolAddress((void**)&qkv, g_qkv);
    cudaGetSymbolAddress((void**)&ff,  g_ff);
    cudaGetSymbolAddress((void**)&o,   g_o);
    cudaGetSymbolAddress((void**)&sc,  g_scores);

    // ---- patch embed ----
    ln_kernel<<<BS, 256>>>(x, ln, pe_ln1_g, pe_ln1_b, INDIM, 1e-6f);
    gemm128<<<dim3(HDIM / 128, BS / 128), 256>>>(ln, pe_w, pe_b, nullptr, ff,
                                                 BS, HDIM, INDIM, 0);
    ln_kernel<<<BS, 256>>>(ff, z, pe_ln2_g, pe_ln2_b, HDIM, 1e-6f);

    // ---- transformer layers ----
    for (int l = 0; l < NLAY; l++) {
        ln_kernel<<<BS, 256>>>(z, ln, lnA_g + (size_t)l * HDIM,
                               lnA_b + (size_t)l * HDIM, HDIM, 1e-5f);
        gemm128<<<dim3(QKVD / 128, BS / 128), 256>>>(
            ln, qkv_w + (size_t)l * QKVD * HDIM, qkv_b + (size_t)l * QKVD,
            nullptr, qkv, BS, QKVD, HDIM, 0);

        scores_kernel<<<dim3(16, 16, NB * NH), 256>>>(qkv, relt, sc);
        softmax_kernel<<<dim3(SLEN, NB * NH), 256>>>(sc);
        av_kernel<<<dim3(16, NB * NH), 256>>>(sc, qkv, o);

        gemm128<<<dim3(HDIM / 128, BS / 128), 256>>>(
            o, out_w + (size_t)l * HDIM * HDIM, out_b + (size_t)l * HDIM,
            z, z, BS, HDIM, HDIM, 0);

        ln_kernel<<<BS, 256>>>(z, ln, lnF_g + (size_t)l * HDIM,
                               lnF_b + (size_t)l * HDIM, HDIM, 1e-5f);
        gemm128<<<dim3(FFD / 128, BS / 128), 256>>>(
            ln, fc1_w + (size_t)l * FFD * HDIM, fc1_b + (size_t)l * FFD,
            nullptr, ff, BS, FFD, HDIM, 1);
        gemm128<<<dim3(HDIM / 128, BS / 128), 256>>>(
            ff, fc2_w + (size_t)l * HDIM * FFD, fc2_b + (size_t)l * HDIM,
            z, z, BS, HDIM, FFD, 0);
    }

    // ---- head ----
    ln_kernel<<<BS, 256>>>(z, ln, final_g, final_b, HDIM, 1e-5f);
    gemm128<<<dim3(1, BS / 128), 256>>>(ln, head_w, head_b, nullptr, out,
                                        BS, NC, HDIM, 0);
}

// round 2
// speedup vs baseline: 1.3918x; 1.3918x over previous
#include <cuda_runtime.h>
#include <math.h>
#include <stdint.h>

// ---------------------------------------------------------------------------
// CausalTransformer: B=2, T=5120, FEAT=256, TIN=5 -> S=1024 patches
// HDIM=1024, N_HEADS=16, HEAD_DIM=64, N_LAYERS=8, FF_DIM=4096, NUM_CLASSES=100
// Round 2: all dense GEMMs on tensor cores (mma.sync tf32), attention SIMT.
// ---------------------------------------------------------------------------

#define SLEN   1024
#define NB     2
#define BS     2048          // NB * SLEN rows
#define HDIM   1024
#define INDIM  1280          // TIN * FEAT
#define QKVD   3072
#define FFD    4096
#define NH     16
#define HD     64
#define NC     100
#define NLAY   8
#define LREL   257

// ------------------------- scratch (device globals) ------------------------
__device__ float g_ln[(size_t)BS * INDIM];
__device__ float g_z[(size_t)BS * HDIM];
__device__ float g_qkv[(size_t)BS * QKVD];
__device__ float g_ff[(size_t)BS * FFD];
__device__ float g_o[(size_t)BS * HDIM];
__device__ float g_scores[(size_t)NB * NH * SLEN * SLEN];   // 128 MB

// ------------------------------- LayerNorm ---------------------------------
__global__ void ln_kernel(const float* __restrict__ in, float* __restrict__ out,
                          const float* __restrict__ g, const float* __restrict__ b,
                          int n, float eps)
{
    int row = blockIdx.x;
    const float* p = in + (size_t)row * n;
    float* o = out + (size_t)row * n;
    int t = threadIdx.x;

    float s = 0.f, ss = 0.f;
    for (int i = t; i < n; i += blockDim.x) {
        float v = p[i];
        s += v; ss += v * v;
    }
    __shared__ float r1[256], r2[256];
    r1[t] = s; r2[t] = ss;
    __syncthreads();
    for (int st = 128; st > 0; st >>= 1) {
        if (t < st) { r1[t] += r1[t + st]; r2[t] += r2[t + st]; }
        __syncthreads();
    }
    float mean = r1[0] / n;
    float var  = r2[0] / n - mean * mean;
    float inv  = rsqrtf(var + eps);
    for (int i = t; i < n; i += blockDim.x)
        o[i] = (p[i] - mean) * inv * g[i] + b[i];
}

// ---------------------------- tf32 helpers ----------------------------------
__device__ __forceinline__ float tf32r(float x)
{
    uint32_t u;
    asm("cvt.rna.tf32.f32 %0, %1;" : "=r"(u) : "f"(x));
    return __uint_as_float(u);
}

__device__ __forceinline__ void mma_tf32(float (&d)[4],
                                         const uint32_t (&a)[4],
                                         const uint32_t (&b)[2])
{
    asm volatile(
        "mma.sync.aligned.m16n8k8.row.col.f32.tf32.tf32.f32 "
        "{%0,%1,%2,%3}, {%4,%5,%6,%7}, {%8,%9}, {%0,%1,%2,%3};\n"
        : "+f"(d[0]), "+f"(d[1]), "+f"(d[2]), "+f"(d[3])
        : "r"(a[0]), "r"(a[1]), "r"(a[2]), "r"(a[3]),
          "r"(b[0]), "r"(b[1]));
}

// --------------- tensor-core GEMM: C = act(A W^T + b) + res -----------------
// A: [M,K] row-major, W: [N,K] row-major, bias: [N], res: [M,N] or null
// act: 0 = none, 1 = exact gelu.  K must be a multiple of 16, M of 128.
// Block tile 128x128, BK=16, 256 threads = 8 warps (4x2), warp tile 32x64.
#define BM 128
#define BN 128
#define BKK 16
#define SST 136   // smem stride (== 8 mod 32 -> conflict-free fragment LDS)

__global__ void gemm_tc(const float* __restrict__ A, const float* __restrict__ W,
                        const float* __restrict__ bias, const float* __restrict__ res,
                        float* __restrict__ C, int M, int N, int K, int act)
{
    __shared__ float As[BKK][SST];
    __shared__ float Ws[BKK][SST];

    int t    = threadIdx.x;
    int lane = t & 31;
    int wid  = t >> 5;
    int wm   = wid & 3;          // 0..3  (32 rows each)
    int wn   = wid >> 2;         // 0..1  (64 cols each)
    int m0   = blockIdx.y * BM;
    int n0   = blockIdx.x * BN;
    int g    = lane >> 2;        // 0..7
    int tt   = lane & 3;         // 0..3

    float acc[2][8][4];
#pragma unroll
    for (int mi = 0; mi < 2; mi++)
#pragma unroll
        for (int ni = 0; ni < 8; ni++)
#pragma unroll
            for (int c = 0; c < 4; c++) acc[mi][ni][c] = 0.f;

    for (int k0 = 0; k0 < K; k0 += BKK) {
        // ---- stage A tile [128 x 16] and W tile [128 x 16] into k-major smem
#pragma unroll
        for (int u = 0; u < 2; u++) {
            int c   = t * 2 + u;          // 0..511
            int row = c >> 2;             // 0..127
            int kc  = (c & 3) * 4;        // 0,4,8,12
            float4 av = *(const float4*)(A + (size_t)(m0 + row) * K + k0 + kc);
            As[kc + 0][row] = tf32r(av.x);
            As[kc + 1][row] = tf32r(av.y);
            As[kc + 2][row] = tf32r(av.z);
            As[kc + 3][row] = tf32r(av.w);

            float4 wv = make_float4(0.f, 0.f, 0.f, 0.f);
            if (n0 + row < N)
                wv = *(const float4*)(W + (size_t)(n0 + row) * K + k0 + kc);
            Ws[kc + 0][row] = tf32r(wv.x);
            Ws[kc + 1][row] = tf32r(wv.y);
            Ws[kc + 2][row] = tf32r(wv.z);
            Ws[kc + 3][row] = tf32r(wv.w);
        }
        __syncthreads();

#pragma unroll
        for (int ks = 0; ks < BKK; ks += 8) {
            uint32_t af[2][4];
            uint32_t bf[8][2];
#pragma unroll
            for (int mi = 0; mi < 2; mi++) {
                int mb = wm * 32 + mi * 16;
                af[mi][0] = __float_as_uint(As[ks + tt    ][mb + g    ]);
                af[mi][1] = __float_as_uint(As[ks + tt    ][mb + g + 8]);
                af[mi][2] = __float_as_uint(As[ks + tt + 4][mb + g    ]);
                af[mi][3] = __float_as_uint(As[ks + tt + 4][mb + g + 8]);
            }
#pragma unroll
            for (int ni = 0; ni < 8; ni++) {
                int nb = wn * 64 + ni * 8;
                bf[ni][0] = __float_as_uint(Ws[ks + tt    ][nb + g]);
                bf[ni][1] = __float_as_uint(Ws[ks + tt + 4][nb + g]);
            }
#pragma unroll
            for (int mi = 0; mi < 2; mi++)
#pragma unroll
                for (int ni = 0; ni < 8; ni++)
                    mma_tf32(acc[mi][ni], af[mi], bf[ni]);
        }
        __syncthreads();
    }

    // ---------------------------- epilogue ----------------------------------
#pragma unroll
    for (int mi = 0; mi < 2; mi++) {
#pragma unroll
        for (int ni = 0; ni < 8; ni++) {
            int m = m0 + wm * 32 + mi * 16 + g;
            int n = n0 + wn * 64 + ni * 8 + tt * 2;
            if (n >= N) continue;   // N even, so pair (n, n+1) fully in-bounds
            float bn0 = bias[n], bn1 = bias[n + 1];
#pragma unroll
            for (int r = 0; r < 2; r++) {     // r=0 -> row m, r=1 -> row m+8
                int mm = m + r * 8;
                float v0 = acc[mi][ni][r * 2 + 0] + bn0;
                float v1 = acc[mi][ni][r * 2 + 1] + bn1;
                if (act == 1) {
                    v0 = 0.5f * v0 * (1.0f + erff(v0 * 0.70710678118654752f));
                    v1 = 0.5f * v1 * (1.0f + erff(v1 * 0.70710678118654752f));
                }
                if (res) {
                    const float2 rv = *(const float2*)(res + (size_t)mm * N + n);
                    v0 += rv.x; v1 += rv.y;
                }
                *(float2*)(C + (size_t)mm * N + n) = make_float2(v0, v1);
            }
        }
    }
}

// ----------------------------- attention scores -----------------------------
__global__ void scores_kernel(const float* __restrict__ qkv,
                              const float* __restrict__ rel,
                              float* __restrict__ scores)
{
    int bh = blockIdx.z, b = bh >> 4, h = bh & 15;
    int q0 = blockIdx.y * 64, k0 = blockIdx.x * 64;
    if (k0 > q0 + 63) return;      // fully above diagonal

    __shared__ float Qs[16][64];
    __shared__ float Ks[16][64];
    int t  = threadIdx.x;
    int lr = t >> 2;
    int lc = (t & 3) * 4;
    int ty = t >> 4, tx = t & 15;

    float acc[4][4];
#pragma unroll
    for (int i = 0; i < 4; i++)
#pragma unroll
        for (int j = 0; j < 4; j++) acc[i][j] = 0.f;

    const float* qbase = qkv + (size_t)(b * SLEN + q0 + lr) * QKVD + h * HD;
    const float* kbase = qkv + (size_t)(b * SLEN + k0 + lr) * QKVD + HDIM + h * HD;

    for (int kk = 0; kk < HD; kk += 16) {
        float4 qv = *(const float4*)(qbase + kk + lc);
        float4 kv = *(const float4*)(kbase + kk + lc);
        Qs[lc + 0][lr] = qv.x; Qs[lc + 1][lr] = qv.y;
        Qs[lc + 2][lr] = qv.z; Qs[lc + 3][lr] = qv.w;
        Ks[lc + 0][lr] = kv.x; Ks[lc + 1][lr] = kv.y;
        Ks[lc + 2][lr] = kv.z; Ks[lc + 3][lr] = kv.w;
        __syncthreads();
#pragma unroll
        for (int k = 0; k < 16; k++) {
            float a[4], w[4];
            *(float4*)a = *(const float4*)&Qs[k][ty * 4];
            *(float4*)w = *(const float4*)&Ks[k][tx * 4];
#pragma unroll
            for (int i = 0; i < 4; i++)
#pragma unroll
                for (int j = 0; j < 4; j++)
                    acc[i][j] = fmaf(a[i], w[j], acc[i][j]);
        }
        __syncthreads();
    }

    float* srow = scores + (size_t)bh * SLEN * SLEN;
#pragma unroll
    for (int i = 0; i < 4; i++) {
        int q = q0 + ty * 4 + i;
#pragma unroll
        for (int j = 0; j < 4; j++) {
            int k = k0 + tx * 4 + j;
            int r = k - q;
            r = min(max(r, -128), 128) + 128;
            float v = acc[i][j] * 0.125f + rel[h * LREL + r];
            if (k > q) v = -1e9f;
            srow[(size_t)q * SLEN + k] = v;
        }
    }
}

// ------------------------------- softmax (causal) ---------------------------
__global__ void softmax_kernel(float* __restrict__ scores)
{
    int q = blockIdx.x, bh = blockIdx.y;
    float* row = scores + (size_t)bh * SLEN * SLEN + (size_t)q * SLEN;
    int n = q + 1;
    int t = threadIdx.x;
    __shared__ float red[256];

    float m = -1e30f;
    for (int i = t; i < n; i += 256) m = fmaxf(m, row[i]);
    red[t] = m; __syncthreads();
    for (int st = 128; st > 0; st >>= 1) {
        if (t < st) red[t] = fmaxf(red[t], red[t + st]);
        __syncthreads();
    }
    m = red[0];
    __syncthreads();

    float s = 0.f;
    for (int i = t; i < n; i += 256) {
        float e = __expf(row[i] - m);
        row[i] = e;
        s += e;
    }
    red[t] = s; __syncthreads();
    for (int st = 128; st > 0; st >>= 1) {
        if (t < st) red[t] += red[t + st];
        __syncthreads();
    }
    float inv = 1.0f / red[0];
    for (int i = t; i < n; i += 256) row[i] *= inv;
}

// ------------------------------ attn @ V ------------------------------------
__global__ void av_kernel(const float* __restrict__ scores,
                          const float* __restrict__ qkv,
                          float* __restrict__ o)
{
    int bh = blockIdx.y, b = bh >> 4, h = bh & 15;
    int q0 = blockIdx.x * 64;

    __shared__ float Ps[32][64];
    __shared__ float Vs[32][64];
    int t  = threadIdx.x;
    int ty = t >> 4, tx = t & 15;
    int pr = t >> 2;
    int pc = (t & 3) * 8;
    int vr = t >> 3;
    int vc = (t & 7) * 8;

    float acc[4][4];
#pragma unroll
    for (int i = 0; i < 4; i++)
#pragma unroll
        for (int j = 0; j < 4; j++) acc[i][j] = 0.f;

    const float* srow = scores + (size_t)bh * SLEN * SLEN;

    for (int kk0 = 0; kk0 < q0 + 64; kk0 += 32) {
        int qg = q0 + pr;
#pragma unroll
        for (int i = 0; i < 8; i += 4) {
            float4 pv = *(const float4*)(srow + (size_t)qg * SLEN + kk0 + pc + i);
            int kb = kk0 + pc + i;
            Ps[pc + i + 0][pr] = (kb + 0 <= qg) ? pv.x : 0.f;
            Ps[pc + i + 1][pr] = (kb + 1 <= qg) ? pv.y : 0.f;
            Ps[pc + i + 2][pr] = (kb + 2 <= qg) ? pv.z : 0.f;
            Ps[pc + i + 3][pr] = (kb + 3 <= qg) ? pv.w : 0.f;
        }
        const float* vbase = qkv + (size_t)(b * SLEN + kk0 + vr) * QKVD
                             + 2 * HDIM + h * HD + vc;
        float4 v0 = *(const float4*)(vbase);
        float4 v1 = *(const float4*)(vbase + 4);
        Vs[vr][vc + 0] = v0.x; Vs[vr][vc + 1] = v0.y;
        Vs[vr][vc + 2] = v0.z; Vs[vr][vc + 3] = v0.w;
        Vs[vr][vc + 4] = v1.x; Vs[vr][vc + 5] = v1.y;
        Vs[vr][vc + 6] = v1.z; Vs[vr][vc + 7] = v1.w;
        __syncthreads();

#pragma unroll
        for (int k = 0; k < 32; k++) {
            float a[4], w[4];
            *(float4*)a = *(const float4*)&Ps[k][ty * 4];
            *(float4*)w = *(const float4*)&Vs[k][tx * 4];
#pragma unroll
            for (int i = 0; i < 4; i++)
#pragma unroll
                for (int j = 0; j < 4; j++)
                    acc[i][j] = fmaf(a[i], w[j], acc[i][j]);
        }
        __syncthreads();
    }

#pragma unroll
    for (int i = 0; i < 4; i++)
#pragma unroll
        for (int j = 0; j < 4; j++)
            o[(size_t)(b * SLEN + q0 + ty * 4 + i) * HDIM + h * HD + tx * 4 + j]
                = acc[i][j];
}

// ------------------------------- launcher -----------------------------------
extern "C" void kernel_launch(void* const* d_in, const int* in_sizes, int n_in,
                              void* d_out, int out_size)
{
    const float* x        = (const float*)d_in[0];
    const float* pe_ln1_g = (const float*)d_in[1];
    const float* pe_ln1_b = (const float*)d_in[2];
    const float* pe_w     = (const float*)d_in[3];
    const float* pe_b     = (const float*)d_in[4];
    const float* pe_ln2_g = (const float*)d_in[5];
    const float* pe_ln2_b = (const float*)d_in[6];
    const float* lnA_g    = (const float*)d_in[7];
    const float* lnA_b    = (const float*)d_in[8];
    const float* qkv_w    = (const float*)d_in[9];
    const float* qkv_b    = (const float*)d_in[10];
    const float* out_w    = (const float*)d_in[11];
    const float* out_b    = (const float*)d_in[12];
    const float* lnF_g    = (const float*)d_in[13];
    const float* lnF_b    = (const float*)d_in[14];
    const float* fc1_w    = (const float*)d_in[15];
    const float* fc1_b    = (const float*)d_in[16];
    const float* fc2_w    = (const float*)d_in[17];
    const float* fc2_b    = (const float*)d_in[18];
    const float* relt     = (const float*)d_in[19];
    const float* final_g  = (const float*)d_in[20];
    const float* final_b  = (const float*)d_in[21];
    const float* head_w   = (const float*)d_in[22];
    const float* head_b   = (const float*)d_in[23];
    float* out = (float*)d_out;

    float *ln, *z, *qkv, *ff, *o, *sc;
    cudaGetSymbolAddress((void**)&ln,  g_ln);
    cudaGetSymbolAddress((void**)&z,   g_z);
    cudaGetSymbolAddress((void**)&qkv, g_qkv);
    cudaGetSymbolAddress((void**)&ff,  g_ff);
    cudaGetSymbolAddress((void**)&o,   g_o);
    cudaGetSymbolAddress((void**)&sc,  g_scores);

    // ---- patch embed ----
    ln_kernel<<<BS, 256>>>(x, ln, pe_ln1_g, pe_ln1_b, INDIM, 1e-6f);
    gemm_tc<<<dim3(HDIM / 128, BS / 128), 256>>>(ln, pe_w, pe_b, nullptr, ff,
                                                 BS, HDIM, INDIM, 0);
    ln_kernel<<<BS, 256>>>(ff, z, pe_ln2_g, pe_ln2_b, HDIM, 1e-6f);

    // ---- transformer layers ----
    for (int l = 0; l < NLAY; l++) {
        ln_kernel<<<BS, 256>>>(z, ln, lnA_g + (size_t)l * HDIM,
                               lnA_b + (size_t)l * HDIM, HDIM, 1e-5f);
        gemm_tc<<<dim3(QKVD / 128, BS / 128), 256>>>(
            ln, qkv_w + (size_t)l * QKVD * HDIM, qkv_b + (size_t)l * QKVD,
            nullptr, qkv, BS, QKVD, HDIM, 0);

        scores_kernel<<<dim3(16, 16, NB * NH), 256>>>(qkv, relt, sc);
        softmax_kernel<<<dim3(SLEN, NB * NH), 256>>>(sc);
        av_kernel<<<dim3(16, NB * NH), 256>>>(sc, qkv, o);

        gemm_tc<<<dim3(HDIM / 128, BS / 128), 256>>>(
            o, out_w + (size_t)l * HDIM * HDIM, out_b + (size_t)l * HDIM,
            z, z, BS, HDIM, HDIM, 0);

        ln_kernel<<<BS, 256>>>(z, ln, lnF_g + (size_t)l * HDIM,
                               lnF_b + (size_t)l * HDIM, HDIM, 1e-5f);
        gemm_tc<<<dim3(FFD / 128, BS / 128), 256>>>(
            ln, fc1_w + (size_t)l * FFD * HDIM, fc1_b + (size_t)l * FFD,
            nullptr, ff, BS, FFD, HDIM, 1);
        gemm_tc<<<dim3(HDIM / 128, BS / 128), 256>>>(
            ff, fc2_w + (size_t)l * HDIM * FFD, fc2_b + (size_t)l * HDIM,
            z, z, BS, HDIM, FFD, 0);
    }

    // ---- head ----
    ln_kernel<<<BS, 256>>>(z, ln, final_g, final_b, HDIM, 1e-5f);
    gemm_tc<<<dim3(1, BS / 128), 256>>>(ln, head_w, head_b, nullptr, out,
                                        BS, NC, HDIM, 0);
}

// round 3
// speedup vs baseline: 2.4625x; 1.7693x over previous
#include <cuda_runtime.h>
#include <math.h>
#include <stdint.h>

// ---------------------------------------------------------------------------
// CausalTransformer: B=2, T=5120, FEAT=256, TIN=5 -> S=1024 patches
// HDIM=1024, N_HEADS=16, HEAD_DIM=64, N_LAYERS=8, FF_DIM=4096, NUM_CLASSES=100
// Round 3: fused flash-attention (tf32 MMA, online softmax), GEMMs unchanged.
// ---------------------------------------------------------------------------

#define SLEN   1024
#define NB     2
#define BS     2048          // NB * SLEN rows
#define HDIM   1024
#define INDIM  1280          // TIN * FEAT
#define QKVD   3072
#define FFD    4096
#define NH     16
#define HD     64
#define NC     100
#define NLAY   8
#define LREL   257

// ------------------------- scratch (device globals) ------------------------
__device__ float g_ln[(size_t)BS * INDIM];
__device__ float g_z[(size_t)BS * HDIM];
__device__ float g_qkv[(size_t)BS * QKVD];
__device__ float g_ff[(size_t)BS * FFD];
__device__ float g_o[(size_t)BS * HDIM];

// ------------------------------- LayerNorm ---------------------------------
__global__ void ln_kernel(const float* __restrict__ in, float* __restrict__ out,
                          const float* __restrict__ g, const float* __restrict__ b,
                          int n, float eps)
{
    int row = blockIdx.x;
    const float* p = in + (size_t)row * n;
    float* o = out + (size_t)row * n;
    int t = threadIdx.x;

    float s = 0.f, ss = 0.f;
    for (int i = t; i < n; i += blockDim.x) {
        float v = p[i];
        s += v; ss += v * v;
    }
    __shared__ float r1[256], r2[256];
    r1[t] = s; r2[t] = ss;
    __syncthreads();
    for (int st = 128; st > 0; st >>= 1) {
        if (t < st) { r1[t] += r1[t + st]; r2[t] += r2[t + st]; }
        __syncthreads();
    }
    float mean = r1[0] / n;
    float var  = r2[0] / n - mean * mean;
    float inv  = rsqrtf(var + eps);
    for (int i = t; i < n; i += blockDim.x)
        o[i] = (p[i] - mean) * inv * g[i] + b[i];
}

// ---------------------------- tf32 helpers ----------------------------------
__device__ __forceinline__ float tf32r(float x)
{
    uint32_t u;
    asm("cvt.rna.tf32.f32 %0, %1;" : "=r"(u) : "f"(x));
    return __uint_as_float(u);
}

__device__ __forceinline__ void mma_tf32(float (&d)[4],
                                         const uint32_t (&a)[4],
                                         const uint32_t (&b)[2])
{
    asm volatile(
        "mma.sync.aligned.m16n8k8.row.col.f32.tf32.tf32.f32 "
        "{%0,%1,%2,%3}, {%4,%5,%6,%7}, {%8,%9}, {%0,%1,%2,%3};\n"
        : "+f"(d[0]), "+f"(d[1]), "+f"(d[2]), "+f"(d[3])
        : "r"(a[0]), "r"(a[1]), "r"(a[2]), "r"(a[3]),
          "r"(b[0]), "r"(b[1]));
}

// --------------- tensor-core GEMM: C = act(A W^T + b) + res -----------------
#define BM 128
#define BN 128
#define BKK 16
#define SST 136   // smem stride (== 8 mod 32 -> conflict-free fragment LDS)

__global__ void gemm_tc(const float* __restrict__ A, const float* __restrict__ W,
                        const float* __restrict__ bias, const float* __restrict__ res,
                        float* __restrict__ C, int M, int N, int K, int act)
{
    __shared__ float As[BKK][SST];
    __shared__ float Ws[BKK][SST];

    int t    = threadIdx.x;
    int lane = t & 31;
    int wid  = t >> 5;
    int wm   = wid & 3;
    int wn   = wid >> 2;
    int m0   = blockIdx.y * BM;
    int n0   = blockIdx.x * BN;
    int g    = lane >> 2;
    int tt   = lane & 3;

    float acc[2][8][4];
#pragma unroll
    for (int mi = 0; mi < 2; mi++)
#pragma unroll
        for (int ni = 0; ni < 8; ni++)
#pragma unroll
            for (int c = 0; c < 4; c++) acc[mi][ni][c] = 0.f;

    for (int k0 = 0; k0 < K; k0 += BKK) {
#pragma unroll
        for (int u = 0; u < 2; u++) {
            int c   = t * 2 + u;
            int row = c >> 2;
            int kc  = (c & 3) * 4;
            float4 av = *(const float4*)(A + (size_t)(m0 + row) * K + k0 + kc);
            As[kc + 0][row] = tf32r(av.x);
            As[kc + 1][row] = tf32r(av.y);
            As[kc + 2][row] = tf32r(av.z);
            As[kc + 3][row] = tf32r(av.w);

            float4 wv = make_float4(0.f, 0.f, 0.f, 0.f);
            if (n0 + row < N)
                wv = *(const float4*)(W + (size_t)(n0 + row) * K + k0 + kc);
            Ws[kc + 0][row] = tf32r(wv.x);
            Ws[kc + 1][row] = tf32r(wv.y);
            Ws[kc + 2][row] = tf32r(wv.z);
            Ws[kc + 3][row] = tf32r(wv.w);
        }
        __syncthreads();

#pragma unroll
        for (int ks = 0; ks < BKK; ks += 8) {
            uint32_t af[2][4];
            uint32_t bf[8][2];
#pragma unroll
            for (int mi = 0; mi < 2; mi++) {
                int mb = wm * 32 + mi * 16;
                af[mi][0] = __float_as_uint(As[ks + tt    ][mb + g    ]);
                af[mi][1] = __float_as_uint(As[ks + tt    ][mb + g + 8]);
                af[mi][2] = __float_as_uint(As[ks + tt + 4][mb + g    ]);
                af[mi][3] = __float_as_uint(As[ks + tt + 4][mb + g + 8]);
            }
#pragma unroll
            for (int ni = 0; ni < 8; ni++) {
                int nb = wn * 64 + ni * 8;
                bf[ni][0] = __float_as_uint(Ws[ks + tt    ][nb + g]);
                bf[ni][1] = __float_as_uint(Ws[ks + tt + 4][nb + g]);
            }
#pragma unroll
            for (int mi = 0; mi < 2; mi++)
#pragma unroll
                for (int ni = 0; ni < 8; ni++)
                    mma_tf32(acc[mi][ni], af[mi], bf[ni]);
        }
        __syncthreads();
    }

#pragma unroll
    for (int mi = 0; mi < 2; mi++) {
#pragma unroll
        for (int ni = 0; ni < 8; ni++) {
            int m = m0 + wm * 32 + mi * 16 + g;
            int n = n0 + wn * 64 + ni * 8 + tt * 2;
            if (n >= N) continue;
            float bn0 = bias[n], bn1 = bias[n + 1];
#pragma unroll
            for (int r = 0; r < 2; r++) {
                int mm = m + r * 8;
                float v0 = acc[mi][ni][r * 2 + 0] + bn0;
                float v1 = acc[mi][ni][r * 2 + 1] + bn1;
                if (act == 1) {
                    v0 = 0.5f * v0 * (1.0f + erff(v0 * 0.70710678118654752f));
                    v1 = 0.5f * v1 * (1.0f + erff(v1 * 0.70710678118654752f));
                }
                if (res) {
                    const float2 rv = *(const float2*)(res + (size_t)mm * N + n);
                    v0 += rv.x; v1 += rv.y;
                }
                *(float2*)(C + (size_t)mm * N + n) = make_float2(v0, v1);
            }
        }
    }
}

// ---------------------- fused flash attention (tf32) ------------------------
// One block per (q-tile of 128, bh). 8 warps, warp w owns q rows w*16..w*16+15.
// QK^T in 3xtf32 (hi/lo compensated) -> fp32-accurate logits.
// Online softmax in registers. PV in single tf32 (rna).
// smem (floats): rel 260 | Ksh 64x72 | Ksl 64x72 | Vs 64x72 | Ps 64x136
#define FA_SMEM_FLOATS (260 + 3 * 64 * 72 + 64 * 136)
#define FA_SMEM_BYTES  (FA_SMEM_FLOATS * 4)

__global__ void __launch_bounds__(256, 1)
flash_kernel(const float* __restrict__ qkv, const float* __restrict__ rel,
             float* __restrict__ o)
{
    extern __shared__ float sm[];
    float* rel_s = sm;                    // 260
    float* Ksh   = sm + 260;              // [d][kk] stride 72
    float* Ksl   = Ksh + 64 * 72;
    float* Vs    = Ksl + 64 * 72;         // [kk][d] stride 72
    float* Ps    = Vs + 64 * 72;          // [k][q]  stride 136

    int bh = blockIdx.y, b = bh >> 4, h = bh & 15;
    int qt = gridDim.x - 1 - blockIdx.x;  // heavy tiles first
    int q0 = qt * 128;
    int t = threadIdx.x, lane = t & 31, w = t >> 5;
    int g = lane >> 2, tt = lane & 3;

    for (int i = t; i < LREL; i += 256) rel_s[i] = rel[h * LREL + i];

    // ---- Q fragments (hi/lo) in registers ----
    uint32_t qhu[8][4], qlu[8][4];
    {
        const float* qp0 = qkv + (size_t)(b * SLEN + q0 + w * 16 + g) * QKVD + h * HD;
        const float* qp1 = qp0 + (size_t)8 * QKVD;
#pragma unroll
        for (int kc = 0; kc < 8; kc++) {
            float v[4];
            v[0] = qp0[kc * 8 + tt];
            v[1] = qp1[kc * 8 + tt];
            v[2] = qp0[kc * 8 + tt + 4];
            v[3] = qp1[kc * 8 + tt + 4];
#pragma unroll
            for (int j = 0; j < 4; j++) {
                float hi = tf32r(v[j]);
                qhu[kc][j] = __float_as_uint(hi);
                qlu[kc][j] = __float_as_uint(tf32r(v[j] - hi));
            }
        }
    }

    float oacc[8][4];
#pragma unroll
    for (int nt = 0; nt < 8; nt++)
#pragma unroll
        for (int c = 0; c < 4; c++) oacc[nt][c] = 0.f;
    float mrow0 = -1e30f, mrow1 = -1e30f;
    float lrow0 = 0.f, lrow1 = 0.f;

    int q_g0 = q0 + w * 16 + g;       // global q for c0,c1
    int q_g1 = q_g0 + 8;              // global q for c2,c3

    int nkt = 2 * qt + 2;
    for (int kt = 0; kt < nkt; kt++) {
        int kk0 = kt * 64;

        // ---- stage K (transposed, hi/lo) and V (tf32-rounded) ----
        {
            int kr = t >> 2;
            int dc = (t & 3) * 16;
            const float* kp = qkv + (size_t)(b * SLEN + kk0 + kr) * QKVD + HDIM + h * HD + dc;
            const float* vp = kp + HDIM;
#pragma unroll
            for (int u = 0; u < 4; u++) {
                float4 k4 = *(const float4*)(kp + u * 4);
                int d0 = dc + u * 4;
                float hx;
                hx = tf32r(k4.x); Ksh[(d0 + 0) * 72 + kr] = hx; Ksl[(d0 + 0) * 72 + kr] = tf32r(k4.x - hx);
                hx = tf32r(k4.y); Ksh[(d0 + 1) * 72 + kr] = hx; Ksl[(d0 + 1) * 72 + kr] = tf32r(k4.y - hx);
                hx = tf32r(k4.z); Ksh[(d0 + 2) * 72 + kr] = hx; Ksl[(d0 + 2) * 72 + kr] = tf32r(k4.z - hx);
                hx = tf32r(k4.w); Ksh[(d0 + 3) * 72 + kr] = hx; Ksl[(d0 + 3) * 72 + kr] = tf32r(k4.w - hx);
                float4 v4 = *(const float4*)(vp + u * 4);
                v4.x = tf32r(v4.x); v4.y = tf32r(v4.y);
                v4.z = tf32r(v4.z); v4.w = tf32r(v4.w);
                *(float4*)(Vs + kr * 72 + d0) = v4;
            }
        }
        __syncthreads();

        // ---- S = Q K^T (3x tf32) ----
        float sc[8][4];
#pragma unroll
        for (int nt = 0; nt < 8; nt++)
#pragma unroll
            for (int c = 0; c < 4; c++) sc[nt][c] = 0.f;

#pragma unroll
        for (int kc = 0; kc < 8; kc++) {
#pragma unroll
            for (int nt = 0; nt < 8; nt++) {
                uint32_t bfh[2], bfl[2];
                bfh[0] = __float_as_uint(Ksh[(kc * 8 + tt)     * 72 + nt * 8 + g]);
                bfh[1] = __float_as_uint(Ksh[(kc * 8 + tt + 4) * 72 + nt * 8 + g]);
                bfl[0] = __float_as_uint(Ksl[(kc * 8 + tt)     * 72 + nt * 8 + g]);
                bfl[1] = __float_as_uint(Ksl[(kc * 8 + tt + 4) * 72 + nt * 8 + g]);
                mma_tf32(sc[nt], qhu[kc], bfh);
                mma_tf32(sc[nt], qhu[kc], bfl);
                mma_tf32(sc[nt], qlu[kc], bfh);
            }
        }

        // ---- bias + causal mask ----
#pragma unroll
        for (int nt = 0; nt < 8; nt++) {
            int k0c = kk0 + nt * 8 + 2 * tt;
#pragma unroll
            for (int j = 0; j < 2; j++) {
                int k = k0c + j;
                int r0 = min(max(k - q_g0, -128), 128) + 128;
                int r1 = min(max(k - q_g1, -128), 128) + 128;
                float s0 = sc[nt][j]     * 0.125f + rel_s[r0];
                float s1 = sc[nt][2 + j] * 0.125f + rel_s[r1];
                sc[nt][j]     = (k > q_g0) ? -1e9f : s0;
                sc[nt][2 + j] = (k > q_g1) ? -1e9f : s1;
            }
        }

        // ---- online softmax ----
        float mx0 = -1e30f, mx1 = -1e30f;
#pragma unroll
        for (int nt = 0; nt < 8; nt++) {
            mx0 = fmaxf(mx0, fmaxf(sc[nt][0], sc[nt][1]));
            mx1 = fmaxf(mx1, fmaxf(sc[nt][2], sc[nt][3]));
        }
        mx0 = fmaxf(mx0, __shfl_xor_sync(0xffffffffu, mx0, 1));
        mx0 = fmaxf(mx0, __shfl_xor_sync(0xffffffffu, mx0, 2));
        mx1 = fmaxf(mx1, __shfl_xor_sync(0xffffffffu, mx1, 1));
        mx1 = fmaxf(mx1, __shfl_xor_sync(0xffffffffu, mx1, 2));
        float mnew0 = fmaxf(mrow0, mx0);
        float mnew1 = fmaxf(mrow1, mx1);
        float scale0 = __expf(mrow0 - mnew0);
        float scale1 = __expf(mrow1 - mnew1);

        float sum0 = 0.f, sum1 = 0.f;
#pragma unroll
        for (int nt = 0; nt < 8; nt++) {
            float p0 = __expf(sc[nt][0] - mnew0);
            float p1 = __expf(sc[nt][1] - mnew0);
            float p2 = __expf(sc[nt][2] - mnew1);
            float p3 = __expf(sc[nt][3] - mnew1);
            sum0 += p0 + p1;
            sum1 += p2 + p3;
            int kc0 = nt * 8 + 2 * tt;
            int qm  = w * 16 + g;
            Ps[(kc0    ) * 136 + qm    ] = tf32r(p0);
            Ps[(kc0 + 1) * 136 + qm    ] = tf32r(p1);
            Ps[(kc0    ) * 136 + qm + 8] = tf32r(p2);
            Ps[(kc0 + 1) * 136 + qm + 8] = tf32r(p3);
        }
        sum0 += __shfl_xor_sync(0xffffffffu, sum0, 1);
        sum0 += __shfl_xor_sync(0xffffffffu, sum0, 2);
        sum1 += __shfl_xor_sync(0xffffffffu, sum1, 1);
        sum1 += __shfl_xor_sync(0xffffffffu, sum1, 2);

        lrow0 = lrow0 * scale0 + sum0;
        lrow1 = lrow1 * scale1 + sum1;
        mrow0 = mnew0; mrow1 = mnew1;
#pragma unroll
        for (int nt = 0; nt < 8; nt++) {
            oacc[nt][0] *= scale0; oacc[nt][1] *= scale0;
            oacc[nt][2] *= scale1; oacc[nt][3] *= scale1;
        }
        __syncwarp();

        // ---- O += P V ----
#pragma unroll
        for (int kc = 0; kc < 8; kc++) {
            uint32_t af[4];
            int mb = w * 16 + g;
            af[0] = __float_as_uint(Ps[(kc * 8 + tt)     * 136 + mb    ]);
            af[1] = __float_as_uint(Ps[(kc * 8 + tt)     * 136 + mb + 8]);
            af[2] = __float_as_uint(Ps[(kc * 8 + tt + 4) * 136 + mb    ]);
            af[3] = __float_as_uint(Ps[(kc * 8 + tt + 4) * 136 + mb + 8]);
#pragma unroll
            for (int nt = 0; nt < 8; nt++) {
                uint32_t bf[2];
                bf[0] = __float_as_uint(Vs[(kc * 8 + tt)     * 72 + nt * 8 + g]);
                bf[1] = __float_as_uint(Vs[(kc * 8 + tt + 4) * 72 + nt * 8 + g]);
                mma_tf32(oacc[nt], af, bf);
            }
        }
        __syncthreads();
    }

    // ---- epilogue: O / l ----
    float inv0 = 1.0f / lrow0;
    float inv1 = 1.0f / lrow1;
    float* op = o + (size_t)(b * SLEN + q_g0) * HDIM + h * HD;
#pragma unroll
    for (int nt = 0; nt < 8; nt++) {
        int d = nt * 8 + 2 * tt;
        *(float2*)(op + d) = make_float2(oacc[nt][0] * inv0, oacc[nt][1] * inv0);
        *(float2*)(op + (size_t)8 * HDIM + d) =
            make_float2(oacc[nt][2] * inv1, oacc[nt][3] * inv1);
    }
}

// ------------------------------- launcher -----------------------------------
extern "C" void kernel_launch(void* const* d_in, const int* in_sizes, int n_in,
                              void* d_out, int out_size)
{
    const float* x        = (const float*)d_in[0];
    const float* pe_ln1_g = (const float*)d_in[1];
    const float* pe_ln1_b = (const float*)d_in[2];
    const float* pe_w     = (const float*)d_in[3];
    const float* pe_b     = (const float*)d_in[4];
    const float* pe_ln2_g = (const float*)d_in[5];
    const float* pe_ln2_b = (const float*)d_in[6];
    const float* lnA_g    = (const float*)d_in[7];
    const float* lnA_b    = (const float*)d_in[8];
    const float* qkv_w    = (const float*)d_in[9];
    const float* qkv_b    = (const float*)d_in[10];
    const float* out_w    = (const float*)d_in[11];
    const float* out_b    = (const float*)d_in[12];
    const float* lnF_g    = (const float*)d_in[13];
    const float* lnF_b    = (const float*)d_in[14];
    const float* fc1_w    = (const float*)d_in[15];
    const float* fc1_b    = (const float*)d_in[16];
    const float* fc2_w    = (const float*)d_in[17];
    const float* fc2_b    = (const float*)d_in[18];
    const float* relt     = (const float*)d_in[19];
    const float* final_g  = (const float*)d_in[20];
    const float* final_b  = (const float*)d_in[21];
    const float* head_w   = (const float*)d_in[22];
    const float* head_b   = (const float*)d_in[23];
    float* out = (float*)d_out;

    float *ln, *z, *qkv, *ff, *o;
    cudaGetSymbolAddress((void**)&ln,  g_ln);
    cudaGetSymbolAddress((void**)&z,   g_z);
    cudaGetSymbolAddress((void**)&qkv, g_qkv);
    cudaGetSymbolAddress((void**)&ff,  g_ff);
    cudaGetSymbolAddress((void**)&o,   g_o);

    cudaFuncSetAttribute(flash_kernel,
                         cudaFuncAttributeMaxDynamicSharedMemorySize,
                         FA_SMEM_BYTES);

    // ---- patch embed ----
    ln_kernel<<<BS, 256>>>(x, ln, pe_ln1_g, pe_ln1_b, INDIM, 1e-6f);
    gemm_tc<<<dim3(HDIM / 128, BS / 128), 256>>>(ln, pe_w, pe_b, nullptr, ff,
                                                 BS, HDIM, INDIM, 0);
    ln_kernel<<<BS, 256>>>(ff, z, pe_ln2_g, pe_ln2_b, HDIM, 1e-6f);

    // ---- transformer layers ----
    for (int l = 0; l < NLAY; l++) {
        ln_kernel<<<BS, 256>>>(z, ln, lnA_g + (size_t)l * HDIM,
                               lnA_b + (size_t)l * HDIM, HDIM, 1e-5f);
        gemm_tc<<<dim3(QKVD / 128, BS / 128), 256>>>(
            ln, qkv_w + (size_t)l * QKVD * HDIM, qkv_b + (size_t)l * QKVD,
            nullptr, qkv, BS, QKVD, HDIM, 0);

        flash_kernel<<<dim3(8, NB * NH), 256, FA_SMEM_BYTES>>>(qkv, relt, o);

        gemm_tc<<<dim3(HDIM / 128, BS / 128), 256>>>(
            o, out_w + (size_t)l * HDIM * HDIM, out_b + (size_t)l * HDIM,
            z, z, BS, HDIM, HDIM, 0);

        ln_kernel<<<BS, 256>>>(z, ln, lnF_g + (size_t)l * HDIM,
                               lnF_b + (size_t)l * HDIM, HDIM, 1e-5f);
        gemm_tc<<<dim3(FFD / 128, BS / 128), 256>>>(
            ln, fc1_w + (size_t)l * FFD * HDIM, fc1_b + (size_t)l * FFD,
            nullptr, ff, BS, FFD, HDIM, 1);
        gemm_tc<<<dim3(HDIM / 128, BS / 128), 256>>>(
            ff, fc2_w + (size_t)l * HDIM * FFD, fc2_b + (size_t)l * HDIM,
            z, z, BS, HDIM, FFD, 0);
    }

    // ---- head ----
    ln_kernel<<<BS, 256>>>(z, ln, final_g, final_b, HDIM, 1e-5f);
    gemm_tc<<<dim3(1, BS / 128), 256>>>(ln, head_w, head_b, nullptr, out,
                                        BS, NC, HDIM, 0);
}

// round 4
// speedup vs baseline: 3.7066x; 1.5052x over previous
#include <cuda_runtime.h>
#include <math.h>
#include <stdint.h>

// ---------------------------------------------------------------------------
// CausalTransformer: B=2, T=5120, FEAT=256, TIN=5 -> S=1024 patches
// HDIM=1024, N_HEADS=16, HEAD_DIM=64, N_LAYERS=8, FF_DIM=4096, NUM_CLASSES=100
// Round 4: cp.async double-buffered tf32 GEMM, pre-rounded operands.
// ---------------------------------------------------------------------------

#define SLEN   1024
#define NB     2
#define BS     2048
#define HDIM   1024
#define INDIM  1280
#define QKVD   3072
#define FFD    4096
#define NH     16
#define HD     64
#define NC     100
#define NLAY   8
#define LREL   257

// ------------------------- scratch (device globals) ------------------------
__device__ float g_ln[(size_t)BS * INDIM];
__device__ float g_z[(size_t)BS * HDIM];
__device__ float g_qkv[(size_t)BS * QKVD];
__device__ float g_ff[(size_t)BS * FFD];
__device__ float g_o[(size_t)BS * HDIM];
// pre-rounded (tf32/rna) weights, concatenated:
// pe | qkv | out | fc1 | fc2 | head
#define WOFF_PE   ((size_t)0)
#define WOFF_QKV  (WOFF_PE  + (size_t)INDIM * HDIM)
#define WOFF_OUT  (WOFF_QKV + (size_t)NLAY * QKVD * HDIM)
#define WOFF_FC1  (WOFF_OUT + (size_t)NLAY * HDIM * HDIM)
#define WOFF_FC2  (WOFF_FC1 + (size_t)NLAY * FFD * HDIM)
#define WOFF_HEAD (WOFF_FC2 + (size_t)NLAY * HDIM * FFD)
#define WTOTAL    (WOFF_HEAD + (size_t)NC * HDIM)
__device__ float g_w[WTOTAL];

// ---------------------------- tf32 helpers ----------------------------------
__device__ __forceinline__ float tf32r(float x)
{
    uint32_t u;
    asm("cvt.rna.tf32.f32 %0, %1;" : "=r"(u) : "f"(x));
    return __uint_as_float(u);
}

__device__ __forceinline__ void mma_tf32(float (&d)[4],
                                         const uint32_t (&a)[4],
                                         const uint32_t (&b)[2])
{
    asm volatile(
        "mma.sync.aligned.m16n8k8.row.col.f32.tf32.tf32.f32 "
        "{%0,%1,%2,%3}, {%4,%5,%6,%7}, {%8,%9}, {%0,%1,%2,%3};\n"
        : "+f"(d[0]), "+f"(d[1]), "+f"(d[2]), "+f"(d[3])
        : "r"(a[0]), "r"(a[1]), "r"(a[2]), "r"(a[3]),
          "r"(b[0]), "r"(b[1]));
}

__device__ __forceinline__ uint32_t smem_u32(const void* p)
{
    uint32_t a;
    asm("{ .reg .u64 t; cvta.to.shared.u64 t, %1; cvt.u32.u64 %0, t; }"
        : "=r"(a) : "l"(p));
    return a;
}

// --------------------------- weight tf32 rounding ---------------------------
__global__ void cvt_kernel(const float* __restrict__ in, float* __restrict__ out,
                           int n4)
{
    for (int i = blockIdx.x * blockDim.x + threadIdx.x; i < n4;
         i += gridDim.x * blockDim.x) {
        float4 v = ((const float4*)in)[i];
        v.x = tf32r(v.x); v.y = tf32r(v.y);
        v.z = tf32r(v.z); v.w = tf32r(v.w);
        ((float4*)out)[i] = v;
    }
}

// ------------------------------- LayerNorm ---------------------------------
// rnd=1 -> output rounded to tf32 (feeds a GEMM A operand only)
__global__ void ln_kernel(const float* __restrict__ in, float* __restrict__ out,
                          const float* __restrict__ g, const float* __restrict__ b,
                          int n, float eps, int rnd)
{
    int row = blockIdx.x;
    const float4* p4 = (const float4*)(in + (size_t)row * n);
    int n4 = n >> 2;
    int t = threadIdx.x, lane = t & 31, w = t >> 5;

    float s = 0.f, ss = 0.f;
    for (int i = t; i < n4; i += 256) {
        float4 v = p4[i];
        s  += v.x + v.y + v.z + v.w;
        ss += v.x * v.x + v.y * v.y + v.z * v.z + v.w * v.w;
    }
#pragma unroll
    for (int off = 16; off > 0; off >>= 1) {
        s  += __shfl_xor_sync(0xffffffffu, s, off);
        ss += __shfl_xor_sync(0xffffffffu, ss, off);
    }
    __shared__ float r1[8], r2[8], bc[2];
    if (lane == 0) { r1[w] = s; r2[w] = ss; }
    __syncthreads();
    if (t == 0) {
        float a = 0.f, c = 0.f;
#pragma unroll
        for (int i = 0; i < 8; i++) { a += r1[i]; c += r2[i]; }
        float mean = a / n;
        float var  = c / n - mean * mean;
        bc[0] = mean;
        bc[1] = rsqrtf(var + eps);
    }
    __syncthreads();
    float mean = bc[0], inv = bc[1];

    float4* o4 = (float4*)(out + (size_t)row * n);
    const float4* g4 = (const float4*)g;
    const float4* b4 = (const float4*)b;
    for (int i = t; i < n4; i += 256) {
        float4 v = p4[i], gg = g4[i], bb = b4[i];
        v.x = (v.x - mean) * inv * gg.x + bb.x;
        v.y = (v.y - mean) * inv * gg.y + bb.y;
        v.z = (v.z - mean) * inv * gg.z + bb.z;
        v.w = (v.w - mean) * inv * gg.w + bb.w;
        if (rnd) {
            v.x = tf32r(v.x); v.y = tf32r(v.y);
            v.z = tf32r(v.z); v.w = tf32r(v.w);
        }
        o4[i] = v;
    }
}

// --------- double-buffered tf32 GEMM: C = act(A W^T + b) + res --------------
// A: [M,K] (already tf32-rounded), W: [N,K] (already tf32-rounded)
// Tile 128x128, BK=32, 2-stage cp.async, 8 warps (4x2), warp tile 32x64.
#define BKD   32
#define WROW  36                       // smem row stride (floats)
#define STAGE_F ((128 + 128) * WROW)   // 9216 floats / stage
#define GDB_SMEM_BYTES (2 * STAGE_F * 4)

#define CP16(dst, src) \
    asm volatile("cp.async.cg.shared.global [%0], [%1], 16;" \
                 :: "r"(dst), "l"(src))

__global__ void __launch_bounds__(256, 2)
gemm_db(const float* __restrict__ A, const float* __restrict__ W,
        const float* __restrict__ bias, const float* __restrict__ res,
        float* __restrict__ C, int M, int N, int K, int act)
{
    extern __shared__ float sm[];
    int t = threadIdx.x, lane = t & 31, wid = t >> 5;
    int wm = wid & 3, wn = wid >> 2;
    int m0 = blockIdx.y * 128, n0 = blockIdx.x * 128;
    int g = lane >> 2, tt = lane & 3;
    uint32_t sbase = smem_u32(sm);

    float acc[2][8][4];
#pragma unroll
    for (int mi = 0; mi < 2; mi++)
#pragma unroll
        for (int ni = 0; ni < 8; ni++)
#pragma unroll
            for (int c = 0; c < 4; c++) acc[mi][ni][c] = 0.f;

    int niter = K / BKD;

    auto stage = [&](int s, int k0) {
#pragma unroll
        for (int u = 0; u < 4; u++) {
            int ch  = t + u * 256;         // 0..1023
            int row = ch >> 3;             // 0..127
            int kc  = (ch & 7) * 4;        // 0..28
            const float* srcA = A + (size_t)(m0 + row) * K + k0 + kc;
            uint32_t dA = sbase + 4 * (s * STAGE_F + row * WROW + kc);
            CP16(dA, srcA);
            int rw = n0 + row; if (rw >= N) rw = N - 1;
            const float* srcW = W + (size_t)rw * K + k0 + kc;
            uint32_t dW = sbase + 4 * (s * STAGE_F + 128 * WROW + row * WROW + kc);
            CP16(dW, srcW);
        }
        asm volatile("cp.async.commit_group;");
    };

    stage(0, 0);
    int s = 0;
    for (int it = 0; it < niter; it++) {
        if (it + 1 < niter) {
            stage(s ^ 1, (it + 1) * BKD);
            asm volatile("cp.async.wait_group 1;");
        } else {
            asm volatile("cp.async.wait_group 0;");
        }
        __syncthreads();

        const float* As_ = sm + s * STAGE_F;
        const float* Ws_ = sm + s * STAGE_F + 128 * WROW;
#pragma unroll
        for (int ks = 0; ks < BKD; ks += 8) {
            uint32_t af[2][4], bf[8][2];
#pragma unroll
            for (int mi = 0; mi < 2; mi++) {
                int r0 = (wm * 32 + mi * 16 + g) * WROW + ks + tt;
                af[mi][0] = __float_as_uint(As_[r0]);
                af[mi][1] = __float_as_uint(As_[r0 + 8 * WROW]);
                af[mi][2] = __float_as_uint(As_[r0 + 4]);
                af[mi][3] = __float_as_uint(As_[r0 + 8 * WROW + 4]);
            }
#pragma unroll
            for (int ni = 0; ni < 8; ni++) {
                int r0 = (wn * 64 + ni * 8 + g) * WROW + ks + tt;
                bf[ni][0] = __float_as_uint(Ws_[r0]);
                bf[ni][1] = __float_as_uint(Ws_[r0 + 4]);
            }
#pragma unroll
            for (int mi = 0; mi < 2; mi++)
#pragma unroll
                for (int ni = 0; ni < 8; ni++)
                    mma_tf32(acc[mi][ni], af[mi], bf[ni]);
        }
        __syncthreads();
        s ^= 1;
    }

    // ---------------------------- epilogue ----------------------------------
#pragma unroll
    for (int mi = 0; mi < 2; mi++) {
#pragma unroll
        for (int ni = 0; ni < 8; ni++) {
            int m = m0 + wm * 32 + mi * 16 + g;
            int n = n0 + wn * 64 + ni * 8 + tt * 2;
            if (n >= N) continue;
            float bn0 = bias[n], bn1 = bias[n + 1];
#pragma unroll
            for (int r = 0; r < 2; r++) {
                int mm = m + r * 8;
                float v0 = acc[mi][ni][r * 2 + 0] + bn0;
                float v1 = acc[mi][ni][r * 2 + 1] + bn1;
                if (act == 1) {
                    v0 = 0.5f * v0 * (1.0f + erff(v0 * 0.70710678118654752f));
                    v1 = 0.5f * v1 * (1.0f + erff(v1 * 0.70710678118654752f));
                    v0 = tf32r(v0); v1 = tf32r(v1);   // feeds fc2 A operand
                }
                if (res) {
                    const float2 rv = *(const float2*)(res + (size_t)mm * N + n);
                    v0 += rv.x; v1 += rv.y;
                }
                *(float2*)(C + (size_t)mm * N + n) = make_float2(v0, v1);
            }
        }
    }
}

// ---------------------- fused flash attention (tf32) ------------------------
#define FA_SMEM_FLOATS (260 + 3 * 64 * 72 + 64 * 136)
#define FA_SMEM_BYTES  (FA_SMEM_FLOATS * 4)

__global__ void __launch_bounds__(256, 1)
flash_kernel(const float* __restrict__ qkv, const float* __restrict__ rel,
             float* __restrict__ o)
{
    extern __shared__ float sm[];
    float* rel_s = sm;
    float* Ksh   = sm + 260;
    float* Ksl   = Ksh + 64 * 72;
    float* Vs    = Ksl + 64 * 72;
    float* Ps    = Vs + 64 * 72;

    int bh = blockIdx.y, b = bh >> 4, h = bh & 15;
    int qt = gridDim.x - 1 - blockIdx.x;
    int q0 = qt * 128;
    int t = threadIdx.x, lane = t & 31, w = t >> 5;
    int g = lane >> 2, tt = lane & 3;

    for (int i = t; i < LREL; i += 256) rel_s[i] = rel[h * LREL + i];

    uint32_t qhu[8][4], qlu[8][4];
    {
        const float* qp0 = qkv + (size_t)(b * SLEN + q0 + w * 16 + g) * QKVD + h * HD;
        const float* qp1 = qp0 + (size_t)8 * QKVD;
#pragma unroll
        for (int kc = 0; kc < 8; kc++) {
            float v[4];
            v[0] = qp0[kc * 8 + tt];
            v[1] = qp1[kc * 8 + tt];
            v[2] = qp0[kc * 8 + tt + 4];
            v[3] = qp1[kc * 8 + tt + 4];
#pragma unroll
            for (int j = 0; j < 4; j++) {
                float hi = tf32r(v[j]);
                qhu[kc][j] = __float_as_uint(hi);
                qlu[kc][j] = __float_as_uint(tf32r(v[j] - hi));
            }
        }
    }

    float oacc[8][4];
#pragma unroll
    for (int nt = 0; nt < 8; nt++)
#pragma unroll
        for (int c = 0; c < 4; c++) oacc[nt][c] = 0.f;
    float mrow0 = -1e30f, mrow1 = -1e30f;
    float lrow0 = 0.f, lrow1 = 0.f;

    int q_g0 = q0 + w * 16 + g;
    int q_g1 = q_g0 + 8;

    int nkt = 2 * qt + 2;
    for (int kt = 0; kt < nkt; kt++) {
        int kk0 = kt * 64;
        {
            int kr = t >> 2;
            int dc = (t & 3) * 16;
            const float* kp = qkv + (size_t)(b * SLEN + kk0 + kr) * QKVD + HDIM + h * HD + dc;
            const float* vp = kp + HDIM;
#pragma unroll
            for (int u = 0; u < 4; u++) {
                float4 k4 = *(const float4*)(kp + u * 4);
                int d0 = dc + u * 4;
                float hx;
                hx = tf32r(k4.x); Ksh[(d0 + 0) * 72 + kr] = hx; Ksl[(d0 + 0) * 72 + kr] = tf32r(k4.x - hx);
                hx = tf32r(k4.y); Ksh[(d0 + 1) * 72 + kr] = hx; Ksl[(d0 + 1) * 72 + kr] = tf32r(k4.y - hx);
                hx = tf32r(k4.z); Ksh[(d0 + 2) * 72 + kr] = hx; Ksl[(d0 + 2) * 72 + kr] = tf32r(k4.z - hx);
                hx = tf32r(k4.w); Ksh[(d0 + 3) * 72 + kr] = hx; Ksl[(d0 + 3) * 72 + kr] = tf32r(k4.w - hx);
                float4 v4 = *(const float4*)(vp + u * 4);
                v4.x = tf32r(v4.x); v4.y = tf32r(v4.y);
                v4.z = tf32r(v4.z); v4.w = tf32r(v4.w);
                *(float4*)(Vs + kr * 72 + d0) = v4;
            }
        }
        __syncthreads();

        float sc[8][4];
#pragma unroll
        for (int nt = 0; nt < 8; nt++)
#pragma unroll
            for (int c = 0; c < 4; c++) sc[nt][c] = 0.f;

#pragma unroll
        for (int kc = 0; kc < 8; kc++) {
#pragma unroll
            for (int nt = 0; nt < 8; nt++) {
                uint32_t bfh[2], bfl[2];
                bfh[0] = __float_as_uint(Ksh[(kc * 8 + tt)     * 72 + nt * 8 + g]);
                bfh[1] = __float_as_uint(Ksh[(kc * 8 + tt + 4) * 72 + nt * 8 + g]);
                bfl[0] = __float_as_uint(Ksl[(kc * 8 + tt)     * 72 + nt * 8 + g]);
                bfl[1] = __float_as_uint(Ksl[(kc * 8 + tt + 4) * 72 + nt * 8 + g]);
                mma_tf32(sc[nt], qhu[kc], bfh);
                mma_tf32(sc[nt], qhu[kc], bfl);
                mma_tf32(sc[nt], qlu[kc], bfh);
            }
        }

#pragma unroll
        for (int nt = 0; nt < 8; nt++) {
            int k0c = kk0 + nt * 8 + 2 * tt;
#pragma unroll
            for (int j = 0; j < 2; j++) {
                int k = k0c + j;
                int r0 = min(max(k - q_g0, -128), 128) + 128;
                int r1 = min(max(k - q_g1, -128), 128) + 128;
                float s0 = sc[nt][j]     * 0.125f + rel_s[r0];
                float s1 = sc[nt][2 + j] * 0.125f + rel_s[r1];
                sc[nt][j]     = (k > q_g0) ? -1e9f : s0;
                sc[nt][2 + j] = (k > q_g1) ? -1e9f : s1;
            }
        }

        float mx0 = -1e30f, mx1 = -1e30f;
#pragma unroll
        for (int nt = 0; nt < 8; nt++) {
            mx0 = fmaxf(mx0, fmaxf(sc[nt][0], sc[nt][1]));
            mx1 = fmaxf(mx1, fmaxf(sc[nt][2], sc[nt][3]));
        }
        mx0 = fmaxf(mx0, __shfl_xor_sync(0xffffffffu, mx0, 1));
        mx0 = fmaxf(mx0, __shfl_xor_sync(0xffffffffu, mx0, 2));
        mx1 = fmaxf(mx1, __shfl_xor_sync(0xffffffffu, mx1, 1));
        mx1 = fmaxf(mx1, __shfl_xor_sync(0xffffffffu, mx1, 2));
        float mnew0 = fmaxf(mrow0, mx0);
        float mnew1 = fmaxf(mrow1, mx1);
        float scale0 = __expf(mrow0 - mnew0);
        float scale1 = __expf(mrow1 - mnew1);

        float sum0 = 0.f, sum1 = 0.f;
#pragma unroll
        for (int nt = 0; nt < 8; nt++) {
            float p0 = __expf(sc[nt][0] - mnew0);
            float p1 = __expf(sc[nt][1] - mnew0);
            float p2 = __expf(sc[nt][2] - mnew1);
            float p3 = __expf(sc[nt][3] - mnew1);
            sum0 += p0 + p1;
            sum1 += p2 + p3;
            int kc0 = nt * 8 + 2 * tt;
            int qm  = w * 16 + g;
            Ps[(kc0    ) * 136 + qm    ] = tf32r(p0);
            Ps[(kc0 + 1) * 136 + qm    ] = tf32r(p1);
            Ps[(kc0    ) * 136 + qm + 8] = tf32r(p2);
            Ps[(kc0 + 1) * 136 + qm + 8] = tf32r(p3);
        }
        sum0 += __shfl_xor_sync(0xffffffffu, sum0, 1);
        sum0 += __shfl_xor_sync(0xffffffffu, sum0, 2);
        sum1 += __shfl_xor_sync(0xffffffffu, sum1, 1);
        sum1 += __shfl_xor_sync(0xffffffffu, sum1, 2);

        lrow0 = lrow0 * scale0 + sum0;
        lrow1 = lrow1 * scale1 + sum1;
        mrow0 = mnew0; mrow1 = mnew1;
#pragma unroll
        for (int nt = 0; nt < 8; nt++) {
            oacc[nt][0] *= scale0; oacc[nt][1] *= scale0;
            oacc[nt][2] *= scale1; oacc[nt][3] *= scale1;
        }
        __syncwarp();

#pragma unroll
        for (int kc = 0; kc < 8; kc++) {
            uint32_t af[4];
            int mb = w * 16 + g;
            af[0] = __float_as_uint(Ps[(kc * 8 + tt)     * 136 + mb    ]);
            af[1] = __float_as_uint(Ps[(kc * 8 + tt)     * 136 + mb + 8]);
            af[2] = __float_as_uint(Ps[(kc * 8 + tt + 4) * 136 + mb    ]);
            af[3] = __float_as_uint(Ps[(kc * 8 + tt + 4) * 136 + mb + 8]);
#pragma unroll
            for (int nt = 0; nt < 8; nt++) {
                uint32_t bf[2];
                bf[0] = __float_as_uint(Vs[(kc * 8 + tt)     * 72 + nt * 8 + g]);
                bf[1] = __float_as_uint(Vs[(kc * 8 + tt + 4) * 72 + nt * 8 + g]);
                mma_tf32(oacc[nt], af, bf);
            }
        }
        __syncthreads();
    }

    // epilogue: O / l, rounded to tf32 (feeds out-proj A operand)
    float inv0 = 1.0f / lrow0;
    float inv1 = 1.0f / lrow1;
    float* op = o + (size_t)(b * SLEN + q_g0) * HDIM + h * HD;
#pragma unroll
    for (int nt = 0; nt < 8; nt++) {
        int d = nt * 8 + 2 * tt;
        *(float2*)(op + d) =
            make_float2(tf32r(oacc[nt][0] * inv0), tf32r(oacc[nt][1] * inv0));
        *(float2*)(op + (size_t)8 * HDIM + d) =
            make_float2(tf32r(oacc[nt][2] * inv1), tf32r(oacc[nt][3] * inv1));
    }
}

// ------------------------------- launcher -----------------------------------
extern "C" void kernel_launch(void* const* d_in, const int* in_sizes, int n_in,
                              void* d_out, int out_size)
{
    const float* x        = (const float*)d_in[0];
    const float* pe_ln1_g = (const float*)d_in[1];
    const float* pe_ln1_b = (const float*)d_in[2];
    const float* pe_w     = (const float*)d_in[3];
    const float* pe_b     = (const float*)d_in[4];
    const float* pe_ln2_g = (const float*)d_in[5];
    const float* pe_ln2_b = (const float*)d_in[6];
    const float* lnA_g    = (const float*)d_in[7];
    const float* lnA_b    = (const float*)d_in[8];
    const float* qkv_w    = (const float*)d_in[9];
    const float* qkv_b    = (const float*)d_in[10];
    const float* out_w    = (const float*)d_in[11];
    const float* out_b    = (const float*)d_in[12];
    const float* lnF_g    = (const float*)d_in[13];
    const float* lnF_b    = (const float*)d_in[14];
    const float* fc1_w    = (const float*)d_in[15];
    const float* fc1_b    = (const float*)d_in[16];
    const float* fc2_w    = (const float*)d_in[17];
    const float* fc2_b    = (const float*)d_in[18];
    const float* relt     = (const float*)d_in[19];
    const float* final_g  = (const float*)d_in[20];
    const float* final_b  = (const float*)d_in[21];
    const float* head_w   = (const float*)d_in[22];
    const float* head_b   = (const float*)d_in[23];
    float* out = (float*)d_out;

    float *ln, *z, *qkv, *ff, *o, *wc;
    cudaGetSymbolAddress((void**)&ln,  g_ln);
    cudaGetSymbolAddress((void**)&z,   g_z);
    cudaGetSymbolAddress((void**)&qkv, g_qkv);
    cudaGetSymbolAddress((void**)&ff,  g_ff);
    cudaGetSymbolAddress((void**)&o,   g_o);
    cudaGetSymbolAddress((void**)&wc,  g_w);

    cudaFuncSetAttribute(flash_kernel,
                         cudaFuncAttributeMaxDynamicSharedMemorySize,
                         FA_SMEM_BYTES);
    cudaFuncSetAttribute(gemm_db,
                         cudaFuncAttributeMaxDynamicSharedMemorySize,
                         GDB_SMEM_BYTES);

    float* w_pe   = wc + WOFF_PE;
    float* w_qkv  = wc + WOFF_QKV;
    float* w_out  = wc + WOFF_OUT;
    float* w_fc1  = wc + WOFF_FC1;
    float* w_fc2  = wc + WOFF_FC2;
    float* w_head = wc + WOFF_HEAD;

    // ---- pre-round all weights to tf32 (rna) ----
    cvt_kernel<<<2048, 256>>>(pe_w,   w_pe,   (int)((size_t)INDIM * HDIM / 4));
    cvt_kernel<<<2048, 256>>>(qkv_w,  w_qkv,  (int)((size_t)NLAY * QKVD * HDIM / 4));
    cvt_kernel<<<2048, 256>>>(out_w,  w_out,  (int)((size_t)NLAY * HDIM * HDIM / 4));
    cvt_kernel<<<2048, 256>>>(fc1_w,  w_fc1,  (int)((size_t)NLAY * FFD * HDIM / 4));
    cvt_kernel<<<2048, 256>>>(fc2_w,  w_fc2,  (int)((size_t)NLAY * HDIM * FFD / 4));
    cvt_kernel<<<2048, 256>>>(head_w, w_head, (int)((size_t)NC * HDIM / 4));

    // ---- patch embed ----
    ln_kernel<<<BS, 256>>>(x, ln, pe_ln1_g, pe_ln1_b, INDIM, 1e-6f, 1);
    gemm_db<<<dim3(HDIM / 128, BS / 128), 256, GDB_SMEM_BYTES>>>(
        ln, w_pe, pe_b, nullptr, ff, BS, HDIM, INDIM, 0);
    ln_kernel<<<BS, 256>>>(ff, z, pe_ln2_g, pe_ln2_b, HDIM, 1e-6f, 0);

    // ---- transformer layers ----
    for (int l = 0; l < NLAY; l++) {
        ln_kernel<<<BS, 256>>>(z, ln, lnA_g + (size_t)l * HDIM,
                               lnA_b + (size_t)l * HDIM, HDIM, 1e-5f, 1);
        gemm_db<<<dim3(QKVD / 128, BS / 128), 256, GDB_SMEM_BYTES>>>(
            ln, w_qkv + (size_t)l * QKVD * HDIM, qkv_b + (size_t)l * QKVD,
            nullptr, qkv, BS, QKVD, HDIM, 0);

        flash_kernel<<<dim3(8, NB * NH), 256, FA_SMEM_BYTES>>>(qkv, relt, o);

        gemm_db<<<dim3(HDIM / 128, BS / 128), 256, GDB_SMEM_BYTES>>>(
            o, w_out + (size_t)l * HDIM * HDIM, out_b + (size_t)l * HDIM,
            z, z, BS, HDIM, HDIM, 0);

        ln_kernel<<<BS, 256>>>(z, ln, lnF_g + (size_t)l * HDIM,
                               lnF_b + (size_t)l * HDIM, HDIM, 1e-5f, 1);
        gemm_db<<<dim3(FFD / 128, BS / 128), 256, GDB_SMEM_BYTES>>>(
            ln, w_fc1 + (size_t)l * FFD * HDIM, fc1_b + (size_t)l * FFD,
            nullptr, ff, BS, FFD, HDIM, 1);
        gemm_db<<<dim3(HDIM / 128, BS / 128), 256, GDB_SMEM_BYTES>>>(
            ff, w_fc2 + (size_t)l * HDIM * FFD, fc2_b + (size_t)l * HDIM,
            z, z, BS, HDIM, FFD, 0);
    }

    // ---- head ----
    ln_kernel<<<BS, 256>>>(z, ln, final_g, final_b, HDIM, 1e-5f, 1);
    gemm_db<<<dim3(1, BS / 128), 256, GDB_SMEM_BYTES>>>(
        ln, w_head, head_b, nullptr, out, BS, NC, HDIM, 0);
}

// round 5
// speedup vs baseline: 3.7592x; 1.0142x over previous
#include <cuda_runtime.h>
#include <math.h>
#include <stdint.h>

// ---------------------------------------------------------------------------
// CausalTransformer: B=2, T=5120, FEAT=256, TIN=5 -> S=1024 patches
// HDIM=1024, N_HEADS=16, HEAD_DIM=64, N_LAYERS=8, FF_DIM=4096, NUM_CLASSES=100
// Round 5: shape-matched GEMM tiles (BN=64/128), 3-stage cp.async, warp-LN.
// ---------------------------------------------------------------------------

#define SLEN   1024
#define NB     2
#define BS     2048
#define HDIM   1024
#define INDIM  1280
#define QKVD   3072
#define FFD    4096
#define NH     16
#define HD     64
#define NC     100
#define NLAY   8
#define LREL   257

// ------------------------- scratch (device globals) ------------------------
__device__ float g_ln[(size_t)BS * INDIM];
__device__ float g_z[(size_t)BS * HDIM];
__device__ float g_qkv[(size_t)BS * QKVD];
__device__ float g_ff[(size_t)BS * FFD];
__device__ float g_o[(size_t)BS * HDIM];
// pre-rounded (tf32/rna) weights, concatenated
#define WOFF_PE   ((size_t)0)
#define WOFF_QKV  (WOFF_PE  + (size_t)INDIM * HDIM)
#define WOFF_OUT  (WOFF_QKV + (size_t)NLAY * QKVD * HDIM)
#define WOFF_FC1  (WOFF_OUT + (size_t)NLAY * HDIM * HDIM)
#define WOFF_FC2  (WOFF_FC1 + (size_t)NLAY * FFD * HDIM)
#define WOFF_HEAD (WOFF_FC2 + (size_t)NLAY * HDIM * FFD)
#define WTOTAL    (WOFF_HEAD + (size_t)NC * HDIM)
__device__ float g_w[WTOTAL];

// ---------------------------- tf32 helpers ----------------------------------
__device__ __forceinline__ float tf32r(float x)
{
    uint32_t u;
    asm("cvt.rna.tf32.f32 %0, %1;" : "=r"(u) : "f"(x));
    return __uint_as_float(u);
}

__device__ __forceinline__ void mma_tf32(float (&d)[4],
                                         const uint32_t (&a)[4],
                                         const uint32_t (&b)[2])
{
    asm volatile(
        "mma.sync.aligned.m16n8k8.row.col.f32.tf32.tf32.f32 "
        "{%0,%1,%2,%3}, {%4,%5,%6,%7}, {%8,%9}, {%0,%1,%2,%3};\n"
        : "+f"(d[0]), "+f"(d[1]), "+f"(d[2]), "+f"(d[3])
        : "r"(a[0]), "r"(a[1]), "r"(a[2]), "r"(a[3]),
          "r"(b[0]), "r"(b[1]));
}

__device__ __forceinline__ uint32_t smem_u32(const void* p)
{
    uint32_t a;
    asm("{ .reg .u64 t; cvta.to.shared.u64 t, %1; cvt.u32.u64 %0, t; }"
        : "=r"(a) : "l"(p));
    return a;
}

// --------------------------- weight tf32 rounding ---------------------------
__global__ void cvt_kernel(const float* __restrict__ in, float* __restrict__ out,
                           int n4)
{
    for (int i = blockIdx.x * blockDim.x + threadIdx.x; i < n4;
         i += gridDim.x * blockDim.x) {
        float4 v = ((const float4*)in)[i];
        v.x = tf32r(v.x); v.y = tf32r(v.y);
        v.z = tf32r(v.z); v.w = tf32r(v.w);
        ((float4*)out)[i] = v;
    }
}

// --------------------------- LayerNorm (warp/row) ---------------------------
__global__ void ln_kernel(const float* __restrict__ in, float* __restrict__ out,
                          const float* __restrict__ g, const float* __restrict__ b,
                          int n, float eps, int rnd)
{
    int w = threadIdx.x >> 5, lane = threadIdx.x & 31;
    int row = blockIdx.x * 8 + w;
    const float4* p4 = (const float4*)(in + (size_t)row * n);
    int n4 = n >> 2;

    float s = 0.f, ss = 0.f;
    for (int i = lane; i < n4; i += 32) {
        float4 v = p4[i];
        s  += v.x + v.y + v.z + v.w;
        ss += v.x * v.x + v.y * v.y + v.z * v.z + v.w * v.w;
    }
#pragma unroll
    for (int off = 16; off > 0; off >>= 1) {
        s  += __shfl_xor_sync(0xffffffffu, s, off);
        ss += __shfl_xor_sync(0xffffffffu, ss, off);
    }
    float mean = s / n;
    float var  = ss / n - mean * mean;
    float inv  = rsqrtf(var + eps);

    float4* o4 = (float4*)(out + (size_t)row * n);
    const float4* g4 = (const float4*)g;
    const float4* b4 = (const float4*)b;
    for (int i = lane; i < n4; i += 32) {
        float4 v = p4[i], gg = g4[i], bb = b4[i];
        v.x = (v.x - mean) * inv * gg.x + bb.x;
        v.y = (v.y - mean) * inv * gg.y + bb.y;
        v.z = (v.z - mean) * inv * gg.z + bb.z;
        v.w = (v.w - mean) * inv * gg.w + bb.w;
        if (rnd) {
            v.x = tf32r(v.x); v.y = tf32r(v.y);
            v.z = tf32r(v.z); v.w = tf32r(v.w);
        }
        o4[i] = v;
    }
}

// --------- 3-stage cp.async tf32 GEMM: C = act(A W^T + b) + res -------------
// A: [M,K] tf32-rounded, W: [N,K] tf32-rounded. Tile 128 x BN, BK=32,
// 8 warps (4x2), warp tile 32 x BN/2. One __syncthreads per K-iter.
#define BKD   32
#define WROW  36

#define CP16(dst, src) \
    asm volatile("cp.async.cg.shared.global [%0], [%1], 16;" \
                 :: "r"(dst), "l"(src))

template<int BN>
__global__ void __launch_bounds__(256, 2)
gemm_db(const float* __restrict__ A, const float* __restrict__ W,
        const float* __restrict__ bias, const float* __restrict__ res,
        float* __restrict__ C, int M, int N, int K, int act)
{
    constexpr int NI    = BN / 16;           // n-mma tiles per warp
    constexpr int STAGE = (128 + BN) * WROW; // floats per stage
    constexpr int WCH   = BN * 8 / 256;      // W float4 chunks per thread

    extern __shared__ float sm[];
    int t = threadIdx.x, lane = t & 31, wid = t >> 5;
    int wm = wid & 3, wn = wid >> 2;
    int m0 = blockIdx.y * 128, n0 = blockIdx.x * BN;
    int g = lane >> 2, tt = lane & 3;
    uint32_t sbase = smem_u32(sm);

    float acc[2][NI][4];
#pragma unroll
    for (int mi = 0; mi < 2; mi++)
#pragma unroll
        for (int ni = 0; ni < NI; ni++)
#pragma unroll
            for (int c = 0; c < 4; c++) acc[mi][ni][c] = 0.f;

    int niter = K / BKD;

    auto stage = [&](int s, int k0) {
        uint32_t sb = sbase + 4 * s * STAGE;
#pragma unroll
        for (int u = 0; u < 4; u++) {            // A: 128 rows x 8 chunks
            int ch  = t + u * 256;
            int row = ch >> 3;
            int kc  = (ch & 7) * 4;
            CP16(sb + 4 * (row * WROW + kc),
                 A + (size_t)(m0 + row) * K + k0 + kc);
        }
#pragma unroll
        for (int u = 0; u < WCH; u++) {          // W: BN rows x 8 chunks
            int ch  = t + u * 256;
            int row = ch >> 3;
            int kc  = (ch & 7) * 4;
            int rw  = n0 + row; if (rw >= N) rw = N - 1;
            CP16(sb + 4 * (128 * WROW + row * WROW + kc),
                 W + (size_t)rw * K + k0 + kc);
        }
        asm volatile("cp.async.commit_group;");
    };

    stage(0, 0);
    if (niter > 1) stage(1, BKD);
    int s = 0;
    for (int it = 0; it < niter; it++) {
        if (it + 1 < niter)
            asm volatile("cp.async.wait_group 1;");
        else
            asm volatile("cp.async.wait_group 0;");
        __syncthreads();

        const float* As_ = sm + s * STAGE;
        const float* Ws_ = As_ + 128 * WROW;
#pragma unroll
        for (int ks = 0; ks < BKD; ks += 8) {
            uint32_t af[2][4], bf[NI][2];
#pragma unroll
            for (int mi = 0; mi < 2; mi++) {
                int r0 = (wm * 32 + mi * 16 + g) * WROW + ks + tt;
                af[mi][0] = __float_as_uint(As_[r0]);
                af[mi][1] = __float_as_uint(As_[r0 + 8 * WROW]);
                af[mi][2] = __float_as_uint(As_[r0 + 4]);
                af[mi][3] = __float_as_uint(As_[r0 + 8 * WROW + 4]);
            }
#pragma unroll
            for (int ni = 0; ni < NI; ni++) {
                int r0 = (wn * (BN / 2) + ni * 8 + g) * WROW + ks + tt;
                bf[ni][0] = __float_as_uint(Ws_[r0]);
                bf[ni][1] = __float_as_uint(Ws_[r0 + 4]);
            }
#pragma unroll
            for (int mi = 0; mi < 2; mi++)
#pragma unroll
                for (int ni = 0; ni < NI; ni++)
                    mma_tf32(acc[mi][ni], af[mi], bf[ni]);
        }

        if (it + 2 < niter) {
            int sn = s + 2; if (sn >= 3) sn -= 3;
            stage(sn, (it + 2) * BKD);
        }
        s = (s + 1 == 3) ? 0 : s + 1;
    }

    // ---------------------------- epilogue ----------------------------------
#pragma unroll
    for (int mi = 0; mi < 2; mi++) {
#pragma unroll
        for (int ni = 0; ni < NI; ni++) {
            int m = m0 + wm * 32 + mi * 16 + g;
            int n = n0 + wn * (BN / 2) + ni * 8 + tt * 2;
            if (n >= N) continue;
            float bn0 = bias[n], bn1 = bias[n + 1];
#pragma unroll
            for (int r = 0; r < 2; r++) {
                int mm = m + r * 8;
                float v0 = acc[mi][ni][r * 2 + 0] + bn0;
                float v1 = acc[mi][ni][r * 2 + 1] + bn1;
                if (act == 1) {
                    v0 = 0.5f * v0 * (1.0f + erff(v0 * 0.70710678118654752f));
                    v1 = 0.5f * v1 * (1.0f + erff(v1 * 0.70710678118654752f));
                    v0 = tf32r(v0); v1 = tf32r(v1);   // feeds fc2 A operand
                }
                if (res) {
                    const float2 rv = *(const float2*)(res + (size_t)mm * N + n);
                    v0 += rv.x; v1 += rv.y;
                }
                *(float2*)(C + (size_t)mm * N + n) = make_float2(v0, v1);
            }
        }
    }
}

#define GDB_SMEM(BN) (3 * (128 + (BN)) * WROW * 4)

// ---------------------- fused flash attention (tf32) ------------------------
#define FA_SMEM_FLOATS (260 + 3 * 64 * 72 + 64 * 136)
#define FA_SMEM_BYTES  (FA_SMEM_FLOATS * 4)

__global__ void __launch_bounds__(256, 1)
flash_kernel(const float* __restrict__ qkv, const float* __restrict__ rel,
             float* __restrict__ o)
{
    extern __shared__ float sm[];
    float* rel_s = sm;
    float* Ksh   = sm + 260;
    float* Ksl   = Ksh + 64 * 72;
    float* Vs    = Ksl + 64 * 72;
    float* Ps    = Vs + 64 * 72;

    int bh = blockIdx.y, b = bh >> 4, h = bh & 15;
    int qt = gridDim.x - 1 - blockIdx.x;
    int q0 = qt * 128;
    int t = threadIdx.x, lane = t & 31, w = t >> 5;
    int g = lane >> 2, tt = lane & 3;

    for (int i = t; i < LREL; i += 256) rel_s[i] = rel[h * LREL + i];

    uint32_t qhu[8][4], qlu[8][4];
    {
        const float* qp0 = qkv + (size_t)(b * SLEN + q0 + w * 16 + g) * QKVD + h * HD;
        const float* qp1 = qp0 + (size_t)8 * QKVD;
#pragma unroll
        for (int kc = 0; kc < 8; kc++) {
            float v[4];
            v[0] = qp0[kc * 8 + tt];
            v[1] = qp1[kc * 8 + tt];
            v[2] = qp0[kc * 8 + tt + 4];
            v[3] = qp1[kc * 8 + tt + 4];
#pragma unroll
            for (int j = 0; j < 4; j++) {
                float hi = tf32r(v[j]);
                qhu[kc][j] = __float_as_uint(hi);
                qlu[kc][j] = __float_as_uint(tf32r(v[j] - hi));
            }
        }
    }

    float oacc[8][4];
#pragma unroll
    for (int nt = 0; nt < 8; nt++)
#pragma unroll
        for (int c = 0; c < 4; c++) oacc[nt][c] = 0.f;
    float mrow0 = -1e30f, mrow1 = -1e30f;
    float lrow0 = 0.f, lrow1 = 0.f;

    int q_g0 = q0 + w * 16 + g;
    int q_g1 = q_g0 + 8;

    int nkt = 2 * qt + 2;
    for (int kt = 0; kt < nkt; kt++) {
        int kk0 = kt * 64;
        {
            int kr = t >> 2;
            int dc = (t & 3) * 16;
            const float* kp = qkv + (size_t)(b * SLEN + kk0 + kr) * QKVD + HDIM + h * HD + dc;
            const float* vp = kp + HDIM;
#pragma unroll
            for (int u = 0; u < 4; u++) {
                float4 k4 = *(const float4*)(kp + u * 4);
                int d0 = dc + u * 4;
                float hx;
                hx = tf32r(k4.x); Ksh[(d0 + 0) * 72 + kr] = hx; Ksl[(d0 + 0) * 72 + kr] = tf32r(k4.x - hx);
                hx = tf32r(k4.y); Ksh[(d0 + 1) * 72 + kr] = hx; Ksl[(d0 + 1) * 72 + kr] = tf32r(k4.y - hx);
                hx = tf32r(k4.z); Ksh[(d0 + 2) * 72 + kr] = hx; Ksl[(d0 + 2) * 72 + kr] = tf32r(k4.z - hx);
                hx = tf32r(k4.w); Ksh[(d0 + 3) * 72 + kr] = hx; Ksl[(d0 + 3) * 72 + kr] = tf32r(k4.w - hx);
                float4 v4 = *(const float4*)(vp + u * 4);
                v4.x = tf32r(v4.x); v4.y = tf32r(v4.y);
                v4.z = tf32r(v4.z); v4.w = tf32r(v4.w);
                *(float4*)(Vs + kr * 72 + d0) = v4;
            }
        }
        __syncthreads();

        float sc[8][4];
#pragma unroll
        for (int nt = 0; nt < 8; nt++)
#pragma unroll
            for (int c = 0; c < 4; c++) sc[nt][c] = 0.f;

#pragma unroll
        for (int kc = 0; kc < 8; kc++) {
#pragma unroll
            for (int nt = 0; nt < 8; nt++) {
                uint32_t bfh[2], bfl[2];
                bfh[0] = __float_as_uint(Ksh[(kc * 8 + tt)     * 72 + nt * 8 + g]);
                bfh[1] = __float_as_uint(Ksh[(kc * 8 + tt + 4) * 72 + nt * 8 + g]);
                bfl[0] = __float_as_uint(Ksl[(kc * 8 + tt)     * 72 + nt * 8 + g]);
                bfl[1] = __float_as_uint(Ksl[(kc * 8 + tt + 4) * 72 + nt * 8 + g]);
                mma_tf32(sc[nt], qhu[kc], bfh);
                mma_tf32(sc[nt], qhu[kc], bfl);
                mma_tf32(sc[nt], qlu[kc], bfh);
            }
        }

#pragma unroll
        for (int nt = 0; nt < 8; nt++) {
            int k0c = kk0 + nt * 8 + 2 * tt;
#pragma unroll
            for (int j = 0; j < 2; j++) {
                int k = k0c + j;
                int r0 = min(max(k - q_g0, -128), 128) + 128;
                int r1 = min(max(k - q_g1, -128), 128) + 128;
                float s0 = sc[nt][j]     * 0.125f + rel_s[r0];
                float s1 = sc[nt][2 + j] * 0.125f + rel_s[r1];
                sc[nt][j]     = (k > q_g0) ? -1e9f : s0;
                sc[nt][2 + j] = (k > q_g1) ? -1e9f : s1;
            }
        }

        float mx0 = -1e30f, mx1 = -1e30f;
#pragma unroll
        for (int nt = 0; nt < 8; nt++) {
            mx0 = fmaxf(mx0, fmaxf(sc[nt][0], sc[nt][1]));
            mx1 = fmaxf(mx1, fmaxf(sc[nt][2], sc[nt][3]));
        }
        mx0 = fmaxf(mx0, __shfl_xor_sync(0xffffffffu, mx0, 1));
        mx0 = fmaxf(mx0, __shfl_xor_sync(0xffffffffu, mx0, 2));
        mx1 = fmaxf(mx1, __shfl_xor_sync(0xffffffffu, mx1, 1));
        mx1 = fmaxf(mx1, __shfl_xor_sync(0xffffffffu, mx1, 2));
        float mnew0 = fmaxf(mrow0, mx0);
        float mnew1 = fmaxf(mrow1, mx1);
        float scale0 = __expf(mrow0 - mnew0);
        float scale1 = __expf(mrow1 - mnew1);

        float sum0 = 0.f, sum1 = 0.f;
#pragma unroll
        for (int nt = 0; nt < 8; nt++) {
            float p0 = __expf(sc[nt][0] - mnew0);
            float p1 = __expf(sc[nt][1] - mnew0);
            float p2 = __expf(sc[nt][2] - mnew1);
            float p3 = __expf(sc[nt][3] - mnew1);
            sum0 += p0 + p1;
            sum1 += p2 + p3;
            int kc0 = nt * 8 + 2 * tt;
            int qm  = w * 16 + g;
            Ps[(kc0    ) * 136 + qm    ] = tf32r(p0);
            Ps[(kc0 + 1) * 136 + qm    ] = tf32r(p1);
            Ps[(kc0    ) * 136 + qm + 8] = tf32r(p2);
            Ps[(kc0 + 1) * 136 + qm + 8] = tf32r(p3);
        }
        sum0 += __shfl_xor_sync(0xffffffffu, sum0, 1);
        sum0 += __shfl_xor_sync(0xffffffffu, sum0, 2);
        sum1 += __shfl_xor_sync(0xffffffffu, sum1, 1);
        sum1 += __shfl_xor_sync(0xffffffffu, sum1, 2);

        lrow0 = lrow0 * scale0 + sum0;
        lrow1 = lrow1 * scale1 + sum1;
        mrow0 = mnew0; mrow1 = mnew1;
#pragma unroll
        for (int nt = 0; nt < 8; nt++) {
            oacc[nt][0] *= scale0; oacc[nt][1] *= scale0;
            oacc[nt][2] *= scale1; oacc[nt][3] *= scale1;
        }
        __syncwarp();

#pragma unroll
        for (int kc = 0; kc < 8; kc++) {
            uint32_t af[4];
            int mb = w * 16 + g;
            af[0] = __float_as_uint(Ps[(kc * 8 + tt)     * 136 + mb    ]);
            af[1] = __float_as_uint(Ps[(kc * 8 + tt)     * 136 + mb + 8]);
            af[2] = __float_as_uint(Ps[(kc * 8 + tt + 4) * 136 + mb    ]);
            af[3] = __float_as_uint(Ps[(kc * 8 + tt + 4) * 136 + mb + 8]);
#pragma unroll
            for (int nt = 0; nt < 8; nt++) {
                uint32_t bf[2];
                bf[0] = __float_as_uint(Vs[(kc * 8 + tt)     * 72 + nt * 8 + g]);
                bf[1] = __float_as_uint(Vs[(kc * 8 + tt + 4) * 72 + nt * 8 + g]);
                mma_tf32(oacc[nt], af, bf);
            }
        }
        __syncthreads();
    }

    float inv0 = 1.0f / lrow0;
    float inv1 = 1.0f / lrow1;
    float* op = o + (size_t)(b * SLEN + q_g0) * HDIM + h * HD;
#pragma unroll
    for (int nt = 0; nt < 8; nt++) {
        int d = nt * 8 + 2 * tt;
        *(float2*)(op + d) =
            make_float2(tf32r(oacc[nt][0] * inv0), tf32r(oacc[nt][1] * inv0));
        *(float2*)(op + (size_t)8 * HDIM + d) =
            make_float2(tf32r(oacc[nt][2] * inv1), tf32r(oacc[nt][3] * inv1));
    }
}

// ------------------------------- launcher -----------------------------------
extern "C" void kernel_launch(void* const* d_in, const int* in_sizes, int n_in,
                              void* d_out, int out_size)
{
    const float* x        = (const float*)d_in[0];
    const float* pe_ln1_g = (const float*)d_in[1];
    const float* pe_ln1_b = (const float*)d_in[2];
    const float* pe_w     = (const float*)d_in[3];
    const float* pe_b     = (const float*)d_in[4];
    const float* pe_ln2_g = (const float*)d_in[5];
    const float* pe_ln2_b = (const float*)d_in[6];
    const float* lnA_g    = (const float*)d_in[7];
    const float* lnA_b    = (const float*)d_in[8];
    const float* qkv_w    = (const float*)d_in[9];
    const float* qkv_b    = (const float*)d_in[10];
    const float* out_w    = (const float*)d_in[11];
    const float* out_b    = (const float*)d_in[12];
    const float* lnF_g    = (const float*)d_in[13];
    const float* lnF_b    = (const float*)d_in[14];
    const float* fc1_w    = (const float*)d_in[15];
    const float* fc1_b    = (const float*)d_in[16];
    const float* fc2_w    = (const float*)d_in[17];
    const float* fc2_b    = (const float*)d_in[18];
    const float* relt     = (const float*)d_in[19];
    const float* final_g  = (const float*)d_in[20];
    const float* final_b  = (const float*)d_in[21];
    const float* head_w   = (const float*)d_in[22];
    const float* head_b   = (const float*)d_in[23];
    float* out = (float*)d_out;

    float *ln, *z, *qkv, *ff, *o, *wc;
    cudaGetSymbolAddress((void**)&ln,  g_ln);
    cudaGetSymbolAddress((void**)&z,   g_z);
    cudaGetSymbolAddress((void**)&qkv, g_qkv);
    cudaGetSymbolAddress((void**)&ff,  g_ff);
    cudaGetSymbolAddress((void**)&o,   g_o);
    cudaGetSymbolAddress((void**)&wc,  g_w);

    cudaFuncSetAttribute(flash_kernel,
                         cudaFuncAttributeMaxDynamicSharedMemorySize,
                         FA_SMEM_BYTES);
    cudaFuncSetAttribute(gemm_db<64>,
                         cudaFuncAttributeMaxDynamicSharedMemorySize,
                         GDB_SMEM(64));
    cudaFuncSetAttribute(gemm_db<128>,
                         cudaFuncAttributeMaxDynamicSharedMemorySize,
                         GDB_SMEM(128));

    float* w_pe   = wc + WOFF_PE;
    float* w_qkv  = wc + WOFF_QKV;
    float* w_out  = wc + WOFF_OUT;
    float* w_fc1  = wc + WOFF_FC1;
    float* w_fc2  = wc + WOFF_FC2;
    float* w_head = wc + WOFF_HEAD;

    // ---- pre-round all weights to tf32 (rna) ----
    cvt_kernel<<<2048, 256>>>(pe_w,   w_pe,   (int)((size_t)INDIM * HDIM / 4));
    cvt_kernel<<<2048, 256>>>(qkv_w,  w_qkv,  (int)((size_t)NLAY * QKVD * HDIM / 4));
    cvt_kernel<<<2048, 256>>>(out_w,  w_out,  (int)((size_t)NLAY * HDIM * HDIM / 4));
    cvt_kernel<<<2048, 256>>>(fc1_w,  w_fc1,  (int)((size_t)NLAY * FFD * HDIM / 4));
    cvt_kernel<<<2048, 256>>>(fc2_w,  w_fc2,  (int)((size_t)NLAY * HDIM * FFD / 4));
    cvt_kernel<<<2048, 256>>>(head_w, w_head, (int)((size_t)NC * HDIM / 4));

    // ---- patch embed ----
    ln_kernel<<<BS / 8, 256>>>(x, ln, pe_ln1_g, pe_ln1_b, INDIM, 1e-6f, 1);
    gemm_db<64><<<dim3(HDIM / 64, BS / 128), 256, GDB_SMEM(64)>>>(
        ln, w_pe, pe_b, nullptr, ff, BS, HDIM, INDIM, 0);
    ln_kernel<<<BS / 8, 256>>>(ff, z, pe_ln2_g, pe_ln2_b, HDIM, 1e-6f, 0);

    // ---- transformer layers ----
    for (int l = 0; l < NLAY; l++) {
        ln_kernel<<<BS / 8, 256>>>(z, ln, lnA_g + (size_t)l * HDIM,
                                   lnA_b + (size_t)l * HDIM, HDIM, 1e-5f, 1);
        gemm_db<64><<<dim3(QKVD / 64, BS / 128), 256, GDB_SMEM(64)>>>(
            ln, w_qkv + (size_t)l * QKVD * HDIM, qkv_b + (size_t)l * QKVD,
            nullptr, qkv, BS, QKVD, HDIM, 0);

        flash_kernel<<<dim3(8, NB * NH), 256, FA_SMEM_BYTES>>>(qkv, relt, o);

        gemm_db<64><<<dim3(HDIM / 64, BS / 128), 256, GDB_SMEM(64)>>>(
            o, w_out + (size_t)l * HDIM * HDIM, out_b + (size_t)l * HDIM,
            z, z, BS, HDIM, HDIM, 0);

        ln_kernel<<<BS / 8, 256>>>(z, ln, lnF_g + (size_t)l * HDIM,
                                   lnF_b + (size_t)l * HDIM, HDIM, 1e-5f, 1);
        gemm_db<128><<<dim3(FFD / 128, BS / 128), 256, GDB_SMEM(128)>>>(
            ln, w_fc1 + (size_t)l * FFD * HDIM, fc1_b + (size_t)l * FFD,
            nullptr, ff, BS, FFD, HDIM, 1);
        gemm_db<64><<<dim3(HDIM / 64, BS / 128), 256, GDB_SMEM(64)>>>(
            ff, w_fc2 + (size_t)l * HDIM * FFD, fc2_b + (size_t)l * HDIM,
            z, z, BS, HDIM, FFD, 0);
    }

    // ---- head ----
    ln_kernel<<<BS / 8, 256>>>(z, ln, final_g, final_b, HDIM, 1e-5f, 1);
    gemm_db<64><<<dim3((NC + 63) / 64, BS / 128), 256, GDB_SMEM(64)>>>(
        ln, w_head, head_b, nullptr, out, BS, NC, HDIM, 0);
}

// round 7
// speedup vs baseline: 5.5878x; 1.4864x over previous
#include <cuda_runtime.h>
#include <cuda_fp16.h>
#include <math.h>
#include <stdint.h>

// ---------------------------------------------------------------------------
// CausalTransformer: B=2, T=5120, FEAT=256, TIN=5 -> S=1024 patches
// HDIM=1024, N_HEADS=16, HEAD_DIM=64, N_LAYERS=8, FF_DIM=4096, NUM_CLASSES=100
// Round 7: all dense GEMMs on fp16 mma.sync (m16n8k16, fp32 accum),
//          3-stage cp.async, flash attention unchanged (tf32-compensated).
// ---------------------------------------------------------------------------

#define SLEN   1024
#define NB     2
#define BS     2048
#define HDIM   1024
#define INDIM  1280
#define QKVD   3072
#define FFD    4096
#define NH     16
#define HD     64
#define NC     100
#define NLAY   8
#define LREL   257

// ------------------------- scratch (device globals) ------------------------
__device__ float  g_z[(size_t)BS * HDIM];
__device__ float  g_qkv[(size_t)BS * QKVD];
__device__ float  g_ff[(size_t)BS * HDIM];        // pe gemm output
__device__ __half g_lnh[(size_t)BS * INDIM];      // LN outputs (GEMM A)
__device__ __half g_oh[(size_t)BS * HDIM];        // attention output (GEMM A)
__device__ __half g_ffh[(size_t)BS * FFD];        // fc1 output (GEMM A)
#define WOFF_PE   ((size_t)0)
#define WOFF_QKV  (WOFF_PE  + (size_t)INDIM * HDIM)
#define WOFF_OUT  (WOFF_QKV + (size_t)NLAY * QKVD * HDIM)
#define WOFF_FC1  (WOFF_OUT + (size_t)NLAY * HDIM * HDIM)
#define WOFF_FC2  (WOFF_FC1 + (size_t)NLAY * FFD * HDIM)
#define WOFF_HEAD (WOFF_FC2 + (size_t)NLAY * HDIM * FFD)
#define WTOTAL    (WOFF_HEAD + (size_t)NC * HDIM)
__device__ __half g_wh[WTOTAL];

// ---------------------------- helpers ---------------------------------------
__device__ __forceinline__ float tf32r(float x)
{
    uint32_t u;
    asm("cvt.rna.tf32.f32 %0, %1;" : "=r"(u) : "f"(x));
    return __uint_as_float(u);
}

__device__ __forceinline__ void mma_tf32(float (&d)[4],
                                         const uint32_t (&a)[4],
                                         const uint32_t (&b)[2])
{
    asm volatile(
        "mma.sync.aligned.m16n8k8.row.col.f32.tf32.tf32.f32 "
        "{%0,%1,%2,%3}, {%4,%5,%6,%7}, {%8,%9}, {%0,%1,%2,%3};\n"
        : "+f"(d[0]), "+f"(d[1]), "+f"(d[2]), "+f"(d[3])
        : "r"(a[0]), "r"(a[1]), "r"(a[2]), "r"(a[3]),
          "r"(b[0]), "r"(b[1]));
}

__device__ __forceinline__ void mma_f16(float (&d)[4],
                                        const uint32_t (&a)[4],
                                        const uint32_t (&b)[2])
{
    asm volatile(
        "mma.sync.aligned.m16n8k16.row.col.f32.f16.f16.f32 "
        "{%0,%1,%2,%3}, {%4,%5,%6,%7}, {%8,%9}, {%0,%1,%2,%3};\n"
        : "+f"(d[0]), "+f"(d[1]), "+f"(d[2]), "+f"(d[3])
        : "r"(a[0]), "r"(a[1]), "r"(a[2]), "r"(a[3]),
          "r"(b[0]), "r"(b[1]));
}

__device__ __forceinline__ uint32_t smem_u32(const void* p)
{
    uint32_t a;
    asm("{ .reg .u64 t; cvta.to.shared.u64 t, %1; cvt.u32.u64 %0, t; }"
        : "=r"(a) : "l"(p));
    return a;
}

#define CP16(dst, src) \
    asm volatile("cp.async.cg.shared.global [%0], [%1], 16;" \
                 :: "r"(dst), "l"(src))

// --------------------------- weight fp16 conversion -------------------------
__global__ void cvt_h(const float* __restrict__ in, __half* __restrict__ out,
                      int n4)
{
    for (int i = blockIdx.x * blockDim.x + threadIdx.x; i < n4;
         i += gridDim.x * blockDim.x) {
        float4 v = ((const float4*)in)[i];
        __half2 h0 = __floats2half2_rn(v.x, v.y);
        __half2 h1 = __floats2half2_rn(v.z, v.w);
        uint2 u;
        u.x = *(uint32_t*)&h0;
        u.y = *(uint32_t*)&h1;
        ((uint2*)out)[i] = u;
    }
}

// --------------------------- LayerNorm (warp/row) ---------------------------
// outH != null -> fp16 output (feeds a GEMM A operand); else fp32 to outF.
__global__ void ln_kernel(const float* __restrict__ in,
                          float* __restrict__ outF, __half* __restrict__ outH,
                          const float* __restrict__ g, const float* __restrict__ b,
                          int n, float eps)
{
    int w = threadIdx.x >> 5, lane = threadIdx.x & 31;
    int row = blockIdx.x * 8 + w;
    const float4* p4 = (const float4*)(in + (size_t)row * n);
    int n4 = n >> 2;

    float s = 0.f, ss = 0.f;
    for (int i = lane; i < n4; i += 32) {
        float4 v = p4[i];
        s  += v.x + v.y + v.z + v.w;
        ss += v.x * v.x + v.y * v.y + v.z * v.z + v.w * v.w;
    }
#pragma unroll
    for (int off = 16; off > 0; off >>= 1) {
        s  += __shfl_xor_sync(0xffffffffu, s, off);
        ss += __shfl_xor_sync(0xffffffffu, ss, off);
    }
    float mean = s / n;
    float var  = ss / n - mean * mean;
    float inv  = rsqrtf(var + eps);

    const float4* g4 = (const float4*)g;
    const float4* b4 = (const float4*)b;
    for (int i = lane; i < n4; i += 32) {
        float4 v = p4[i], gg = g4[i], bb = b4[i];
        v.x = (v.x - mean) * inv * gg.x + bb.x;
        v.y = (v.y - mean) * inv * gg.y + bb.y;
        v.z = (v.z - mean) * inv * gg.z + bb.z;
        v.w = (v.w - mean) * inv * gg.w + bb.w;
        if (outH) {
            __half2 h0 = __floats2half2_rn(v.x, v.y);
            __half2 h1 = __floats2half2_rn(v.z, v.w);
            uint2 u;
            u.x = *(uint32_t*)&h0;
            u.y = *(uint32_t*)&h1;
            *(uint2*)(outH + (size_t)row * n + i * 4) = u;
        } else {
            *(float4*)(outF + (size_t)row * n + i * 4) = v;
        }
    }
}

// -------- 3-stage cp.async fp16 GEMM: C = act(A W^T + b) + res --------------
// A: [M,K] fp16, W: [N,K] fp16. Tile 128x128, BK=32, 8 warps (4x2),
// warp tile 32x64, m16n8k16. Output: fp32 (Cf) or fp16 (Ch).
#define BKH   32
#define SH    40                      // halves per smem row (32 data + 8 pad)
#define HSTAGE ((128 + 128) * SH)     // halves per stage
#define GH_SMEM (3 * HSTAGE * 2)      // bytes

__global__ void __launch_bounds__(256, 2)
gemm_h(const __half* __restrict__ A, const __half* __restrict__ W,
       const float* __restrict__ bias, const float* __restrict__ res,
       float* __restrict__ Cf, __half* __restrict__ Ch,
       int M, int N, int K, int act)
{
    extern __shared__ __half smh[];
    int t = threadIdx.x, lane = t & 31, wid = t >> 5;
    int wm = wid & 3, wn = wid >> 2;
    int m0 = blockIdx.y * 128, n0 = blockIdx.x * 128;
    int g = lane >> 2, tt = lane & 3;
    uint32_t sbase = smem_u32(smh);

    float acc[2][8][4];
#pragma unroll
    for (int mi = 0; mi < 2; mi++)
#pragma unroll
        for (int ni = 0; ni < 8; ni++)
#pragma unroll
            for (int c = 0; c < 4; c++) acc[mi][ni][c] = 0.f;

    int niter = K / BKH;

    auto stage = [&](int s, int k0) {
        uint32_t sb = sbase + 2 * s * HSTAGE;
#pragma unroll
        for (int u = 0; u < 4; u++) {
            int i   = t + u * 256;          // 0..1023
            int row = (i >> 2) & 127;
            int seg = i & 3;                // 4 x 16B per 32-half row
            int isB = i >> 9;
            uint32_t dst = sb + (uint32_t)(isB * (128 * SH * 2))
                         + (uint32_t)(row * (SH * 2) + seg * 16);
            const __half* src;
            if (isB) {
                int rw = n0 + row; if (rw >= N) rw = N - 1;
                src = W + (size_t)rw * K + k0 + seg * 8;
            } else {
                src = A + (size_t)(m0 + row) * K + k0 + seg * 8;
            }
            CP16(dst, src);
        }
        asm volatile("cp.async.commit_group;");
    };

    stage(0, 0);
    if (niter > 1) stage(1, BKH);
    int s = 0;
    for (int it = 0; it < niter; it++) {
        if (it + 1 < niter)
            asm volatile("cp.async.wait_group 1;");
        else
            asm volatile("cp.async.wait_group 0;");
        __syncthreads();

        const __half* As_ = smh + s * HSTAGE;
        const __half* Ws_ = As_ + 128 * SH;
#pragma unroll
        for (int ks = 0; ks < BKH; ks += 16) {
            uint32_t af[2][4], bf[8][2];
#pragma unroll
            for (int mi = 0; mi < 2; mi++) {
                int r0 = (wm * 32 + mi * 16 + g) * SH + ks + 2 * tt;
                af[mi][0] = *(const uint32_t*)&As_[r0];
                af[mi][1] = *(const uint32_t*)&As_[r0 + 8 * SH];
                af[mi][2] = *(const uint32_t*)&As_[r0 + 8];
                af[mi][3] = *(const uint32_t*)&As_[r0 + 8 * SH + 8];
            }
#pragma unroll
            for (int ni = 0; ni < 8; ni++) {
                int r0 = (wn * 64 + ni * 8 + g) * SH + ks + 2 * tt;
                bf[ni][0] = *(const uint32_t*)&Ws_[r0];
                bf[ni][1] = *(const uint32_t*)&Ws_[r0 + 8];
            }
#pragma unroll
            for (int mi = 0; mi < 2; mi++)
#pragma unroll
                for (int ni = 0; ni < 8; ni++)
                    mma_f16(acc[mi][ni], af[mi], bf[ni]);
        }

        if (it + 2 < niter) {
            int sn = s + 2; if (sn >= 3) sn -= 3;
            stage(sn, (it + 2) * BKH);
        }
        s = (s + 1 == 3) ? 0 : s + 1;
    }

    // ---------------------------- epilogue ----------------------------------
#pragma unroll
    for (int mi = 0; mi < 2; mi++) {
#pragma unroll
        for (int ni = 0; ni < 8; ni++) {
            int m = m0 + wm * 32 + mi * 16 + g;
            int n = n0 + wn * 64 + ni * 8 + tt * 2;
            if (n >= N) continue;
            float bn0 = bias[n], bn1 = bias[n + 1];
#pragma unroll
            for (int r = 0; r < 2; r++) {
                int mm = m + r * 8;
                float v0 = acc[mi][ni][r * 2 + 0] + bn0;
                float v1 = acc[mi][ni][r * 2 + 1] + bn1;
                if (act == 1) {
                    v0 = 0.5f * v0 * (1.0f + erff(v0 * 0.70710678118654752f));
                    v1 = 0.5f * v1 * (1.0f + erff(v1 * 0.70710678118654752f));
                }
                if (res) {
                    const float2 rv = *(const float2*)(res + (size_t)mm * N + n);
                    v0 += rv.x; v1 += rv.y;
                }
                if (Ch) {
                    __half2 h = __floats2half2_rn(v0, v1);
                    *(__half2*)(Ch + (size_t)mm * N + n) = h;
                } else {
                    *(float2*)(Cf + (size_t)mm * N + n) = make_float2(v0, v1);
                }
            }
        }
    }
}

// ---------------------- fused flash attention (tf32) ------------------------
#define FA_SMEM_FLOATS (260 + 3 * 64 * 72 + 64 * 136)
#define FA_SMEM_BYTES  (FA_SMEM_FLOATS * 4)

__global__ void __launch_bounds__(256, 1)
flash_kernel(const float* __restrict__ qkv, const float* __restrict__ rel,
             __half* __restrict__ o)
{
    extern __shared__ float sm[];
    float* rel_s = sm;
    float* Ksh   = sm + 260;
    float* Ksl   = Ksh + 64 * 72;
    float* Vs    = Ksl + 64 * 72;
    float* Ps    = Vs + 64 * 72;

    int bh = blockIdx.y, b = bh >> 4, h = bh & 15;
    int qt = gridDim.x - 1 - blockIdx.x;
    int q0 = qt * 128;
    int t = threadIdx.x, lane = t & 31, w = t >> 5;
    int g = lane >> 2, tt = lane & 3;

    for (int i = t; i < LREL; i += 256) rel_s[i] = rel[h * LREL + i];

    uint32_t qhu[8][4], qlu[8][4];
    {
        const float* qp0 = qkv + (size_t)(b * SLEN + q0 + w * 16 + g) * QKVD + h * HD;
        const float* qp1 = qp0 + (size_t)8 * QKVD;
#pragma unroll
        for (int kc = 0; kc < 8; kc++) {
            float v[4];
            v[0] = qp0[kc * 8 + tt];
            v[1] = qp1[kc * 8 + tt];
            v[2] = qp0[kc * 8 + tt + 4];
            v[3] = qp1[kc * 8 + tt + 4];
#pragma unroll
            for (int j = 0; j < 4; j++) {
                float hi = tf32r(v[j]);
                qhu[kc][j] = __float_as_uint(hi);
                qlu[kc][j] = __float_as_uint(tf32r(v[j] - hi));
            }
        }
    }

    float oacc[8][4];
#pragma unroll
    for (int nt = 0; nt < 8; nt++)
#pragma unroll
        for (int c = 0; c < 4; c++) oacc[nt][c] = 0.f;
    float mrow0 = -1e30f, mrow1 = -1e30f;
    float lrow0 = 0.f, lrow1 = 0.f;

    int q_g0 = q0 + w * 16 + g;
    int q_g1 = q_g0 + 8;

    int nkt = 2 * qt + 2;
    for (int kt = 0; kt < nkt; kt++) {
        int kk0 = kt * 64;
        {
            int kr = t >> 2;
            int dc = (t & 3) * 16;
            const float* kp = qkv + (size_t)(b * SLEN + kk0 + kr) * QKVD + HDIM + h * HD + dc;
            const float* vp = kp + HDIM;
#pragma unroll
            for (int u = 0; u < 4; u++) {
                float4 k4 = *(const float4*)(kp + u * 4);
                int d0 = dc + u * 4;
                float hx;
                hx = tf32r(k4.x); Ksh[(d0 + 0) * 72 + kr] = hx; Ksl[(d0 + 0) * 72 + kr] = tf32r(k4.x - hx);
                hx = tf32r(k4.y); Ksh[(d0 + 1) * 72 + kr] = hx; Ksl[(d0 + 1) * 72 + kr] = tf32r(k4.y - hx);
                hx = tf32r(k4.z); Ksh[(d0 + 2) * 72 + kr] = hx; Ksl[(d0 + 2) * 72 + kr] = tf32r(k4.z - hx);
                hx = tf32r(k4.w); Ksh[(d0 + 3) * 72 + kr] = hx; Ksl[(d0 + 3) * 72 + kr] = tf32r(k4.w - hx);
                float4 v4 = *(const float4*)(vp + u * 4);
                v4.x = tf32r(v4.x); v4.y = tf32r(v4.y);
                v4.z = tf32r(v4.z); v4.w = tf32r(v4.w);
                *(float4*)(Vs + kr * 72 + d0) = v4;
            }
        }
        __syncthreads();

        float sc[8][4];
#pragma unroll
        for (int nt = 0; nt < 8; nt++)
#pragma unroll
            for (int c = 0; c < 4; c++) sc[nt][c] = 0.f;

#pragma unroll
        for (int kc = 0; kc < 8; kc++) {
#pragma unroll
            for (int nt = 0; nt < 8; nt++) {
                uint32_t bfh[2], bfl[2];
                bfh[0] = __float_as_uint(Ksh[(kc * 8 + tt)     * 72 + nt * 8 + g]);
                bfh[1] = __float_as_uint(Ksh[(kc * 8 + tt + 4) * 72 + nt * 8 + g]);
                bfl[0] = __float_as_uint(Ksl[(kc * 8 + tt)     * 72 + nt * 8 + g]);
                bfl[1] = __float_as_uint(Ksl[(kc * 8 + tt + 4) * 72 + nt * 8 + g]);
                mma_tf32(sc[nt], qhu[kc], bfh);
                mma_tf32(sc[nt], qhu[kc], bfl);
                mma_tf32(sc[nt], qlu[kc], bfh);
            }
        }

#pragma unroll
        for (int nt = 0; nt < 8; nt++) {
            int k0c = kk0 + nt * 8 + 2 * tt;
#pragma unroll
            for (int j = 0; j < 2; j++) {
                int k = k0c + j;
                int r0 = min(max(k - q_g0, -128), 128) + 128;
                int r1 = min(max(k - q_g1, -128), 128) + 128;
                float s0 = sc[nt][j]     * 0.125f + rel_s[r0];
                float s1 = sc[nt][2 + j] * 0.125f + rel_s[r1];
                sc[nt][j]     = (k > q_g0) ? -1e9f : s0;
                sc[nt][2 + j] = (k > q_g1) ? -1e9f : s1;
            }
        }

        float mx0 = -1e30f, mx1 = -1e30f;
#pragma unroll
        for (int nt = 0; nt < 8; nt++) {
            mx0 = fmaxf(mx0, fmaxf(sc[nt][0], sc[nt][1]));
            mx1 = fmaxf(mx1, fmaxf(sc[nt][2], sc[nt][3]));
        }
        mx0 = fmaxf(mx0, __shfl_xor_sync(0xffffffffu, mx0, 1));
        mx0 = fmaxf(mx0, __shfl_xor_sync(0xffffffffu, mx0, 2));
        mx1 = fmaxf(mx1, __shfl_xor_sync(0xffffffffu, mx1, 1));
        mx1 = fmaxf(mx1, __shfl_xor_sync(0xffffffffu, mx1, 2));
        float mnew0 = fmaxf(mrow0, mx0);
        float mnew1 = fmaxf(mrow1, mx1);
        float scale0 = __expf(mrow0 - mnew0);
        float scale1 = __expf(mrow1 - mnew1);

        float sum0 = 0.f, sum1 = 0.f;
#pragma unroll
        for (int nt = 0; nt < 8; nt++) {
            float p0 = __expf(sc[nt][0] - mnew0);
            float p1 = __expf(sc[nt][1] - mnew0);
            float p2 = __expf(sc[nt][2] - mnew1);
            float p3 = __expf(sc[nt][3] - mnew1);
            sum0 += p0 + p1;
            sum1 += p2 + p3;
            int kc0 = nt * 8 + 2 * tt;
            int qm  = w * 16 + g;
            Ps[(kc0    ) * 136 + qm    ] = tf32r(p0);
            Ps[(kc0 + 1) * 136 + qm    ] = tf32r(p1);
            Ps[(kc0    ) * 136 + qm + 8] = tf32r(p2);
            Ps[(kc0 + 1) * 136 + qm + 8] = tf32r(p3);
        }
        sum0 += __shfl_xor_sync(0xffffffffu, sum0, 1);
        sum0 += __shfl_xor_sync(0xffffffffu, sum0, 2);
        sum1 += __shfl_xor_sync(0xffffffffu, sum1, 1);
        sum1 += __shfl_xor_sync(0xffffffffu, sum1, 2);

        lrow0 = lrow0 * scale0 + sum0;
        lrow1 = lrow1 * scale1 + sum1;
        mrow0 = mnew0; mrow1 = mnew1;
#pragma unroll
        for (int nt = 0; nt < 8; nt++) {
            oacc[nt][0] *= scale0; oacc[nt][1] *= scale0;
            oacc[nt][2] *= scale1; oacc[nt][3] *= scale1;
        }
        __syncwarp();

#pragma unroll
        for (int kc = 0; kc < 8; kc++) {
            uint32_t af[4];
            int mb = w * 16 + g;
            af[0] = __float_as_uint(Ps[(kc * 8 + tt)     * 136 + mb    ]);
            af[1] = __float_as_uint(Ps[(kc * 8 + tt)     * 136 + mb + 8]);
            af[2] = __float_as_uint(Ps[(kc * 8 + tt + 4) * 136 + mb    ]);
            af[3] = __float_as_uint(Ps[(kc * 8 + tt + 4) * 136 + mb + 8]);
#pragma unroll
            for (int nt = 0; nt < 8; nt++) {
                uint32_t bf[2];
                bf[0] = __float_as_uint(Vs[(kc * 8 + tt)     * 72 + nt * 8 + g]);
                bf[1] = __float_as_uint(Vs[(kc * 8 + tt + 4) * 72 + nt * 8 + g]);
                mma_tf32(oacc[nt], af, bf);
            }
        }
        __syncthreads();
    }

    // epilogue: O / l -> fp16 (feeds out-proj A operand)
    float inv0 = 1.0f / lrow0;
    float inv1 = 1.0f / lrow1;
    __half* op = o + (size_t)(b * SLEN + q_g0) * HDIM + h * HD;
#pragma unroll
    for (int nt = 0; nt < 8; nt++) {
        int d = nt * 8 + 2 * tt;
        *(__half2*)(op + d) =
            __floats2half2_rn(oacc[nt][0] * inv0, oacc[nt][1] * inv0);
        *(__half2*)(op + (size_t)8 * HDIM + d) =
            __floats2half2_rn(oacc[nt][2] * inv1, oacc[nt][3] * inv1);
    }
}

// ------------------------------- launcher -----------------------------------
extern "C" void kernel_launch(void* const* d_in, const int* in_sizes, int n_in,
                              void* d_out, int out_size)
{
    const float* x        = (const float*)d_in[0];
    const float* pe_ln1_g = (const float*)d_in[1];
    const float* pe_ln1_b = (const float*)d_in[2];
    const float* pe_w     = (const float*)d_in[3];
    const float* pe_b     = (const float*)d_in[4];
    const float* pe_ln2_g = (const float*)d_in[5];
    const float* pe_ln2_b = (const float*)d_in[6];
    const float* lnA_g    = (const float*)d_in[7];
    const float* lnA_b    = (const float*)d_in[8];
    const float* qkv_w    = (const float*)d_in[9];
    const float* qkv_b    = (const float*)d_in[10];
    const float* out_w    = (const float*)d_in[11];
    const float* out_b    = (const float*)d_in[12];
    const float* lnF_g    = (const float*)d_in[13];
    const float* lnF_b    = (const float*)d_in[14];
    const float* fc1_w    = (const float*)d_in[15];
    const float* fc1_b    = (const float*)d_in[16];
    const float* fc2_w    = (const float*)d_in[17];
    const float* fc2_b    = (const float*)d_in[18];
    const float* relt     = (const float*)d_in[19];
    const float* final_g  = (const float*)d_in[20];
    const float* final_b  = (const float*)d_in[21];
    const float* head_w   = (const float*)d_in[22];
    const float* head_b   = (const float*)d_in[23];
    float* out = (float*)d_out;

    float *z, *qkv, *ff;
    __half *lnh, *oh, *ffh, *wh;
    cudaGetSymbolAddress((void**)&z,   g_z);
    cudaGetSymbolAddress((void**)&qkv, g_qkv);
    cudaGetSymbolAddress((void**)&ff,  g_ff);
    cudaGetSymbolAddress((void**)&lnh, g_lnh);
    cudaGetSymbolAddress((void**)&oh,  g_oh);
    cudaGetSymbolAddress((void**)&ffh, g_ffh);
    cudaGetSymbolAddress((void**)&wh,  g_wh);

    cudaFuncSetAttribute(flash_kernel,
                         cudaFuncAttributeMaxDynamicSharedMemorySize,
                         FA_SMEM_BYTES);
    cudaFuncSetAttribute(gemm_h,
                         cudaFuncAttributeMaxDynamicSharedMemorySize,
                         GH_SMEM);

    __half* wh_pe   = wh + WOFF_PE;
    __half* wh_qkv  = wh + WOFF_QKV;
    __half* wh_out  = wh + WOFF_OUT;
    __half* wh_fc1  = wh + WOFF_FC1;
    __half* wh_fc2  = wh + WOFF_FC2;
    __half* wh_head = wh + WOFF_HEAD;

    // ---- convert all weights to fp16 (rn) ----
    cvt_h<<<2048, 256>>>(pe_w,   wh_pe,   (int)((size_t)INDIM * HDIM / 4));
    cvt_h<<<2048, 256>>>(qkv_w,  wh_qkv,  (int)((size_t)NLAY * QKVD * HDIM / 4));
    cvt_h<<<2048, 256>>>(out_w,  wh_out,  (int)((size_t)NLAY * HDIM * HDIM / 4));
    cvt_h<<<2048, 256>>>(fc1_w,  wh_fc1,  (int)((size_t)NLAY * FFD * HDIM / 4));
    cvt_h<<<2048, 256>>>(fc2_w,  wh_fc2,  (int)((size_t)NLAY * HDIM * FFD / 4));
    cvt_h<<<2048, 256>>>(head_w, wh_head, (int)((size_t)NC * HDIM / 4));

    // ---- patch embed ----
    ln_kernel<<<BS / 8, 256>>>(x, nullptr, lnh, pe_ln1_g, pe_ln1_b, INDIM, 1e-6f);
    gemm_h<<<dim3(HDIM / 128, BS / 128), 256, GH_SMEM>>>(
        lnh, wh_pe, pe_b, nullptr, ff, nullptr, BS, HDIM, INDIM, 0);
    ln_kernel<<<BS / 8, 256>>>(ff, z, nullptr, pe_ln2_g, pe_ln2_b, HDIM, 1e-6f);

    // ---- transformer layers ----
    for (int l = 0; l < NLAY; l++) {
        ln_kernel<<<BS / 8, 256>>>(z, nullptr, lnh, lnA_g + (size_t)l * HDIM,
                                   lnA_b + (size_t)l * HDIM, HDIM, 1e-5f);
        gemm_h<<<dim3(QKVD / 128, BS / 128), 256, GH_SMEM>>>(
            lnh, wh_qkv + (size_t)l * QKVD * HDIM, qkv_b + (size_t)l * QKVD,
            nullptr, qkv, nullptr, BS, QKVD, HDIM, 0);

        flash_kernel<<<dim3(8, NB * NH), 256, FA_SMEM_BYTES>>>(qkv, relt, oh);

        gemm_h<<<dim3(HDIM / 128, BS / 128), 256, GH_SMEM>>>(
            oh, wh_out + (size_t)l * HDIM * HDIM, out_b + (size_t)l * HDIM,
            z, z, nullptr, BS, HDIM, HDIM, 0);

        ln_kernel<<<BS / 8, 256>>>(z, nullptr, lnh, lnF_g + (size_t)l * HDIM,
                                   lnF_b + (size_t)l * HDIM, HDIM, 1e-5f);
        gemm_h<<<dim3(FFD / 128, BS / 128), 256, GH_SMEM>>>(
            lnh, wh_fc1 + (size_t)l * FFD * HDIM, fc1_b + (size_t)l * FFD,
            nullptr, nullptr, ffh, BS, FFD, HDIM, 1);
        gemm_h<<<dim3(HDIM / 128, BS / 128), 256, GH_SMEM>>>(
            ffh, wh_fc2 + (size_t)l * HDIM * FFD, fc2_b + (size_t)l * HDIM,
            z, z, nullptr, BS, HDIM, FFD, 0);
    }

    // ---- head ----
    ln_kernel<<<BS / 8, 256>>>(z, nullptr, lnh, final_g, final_b, HDIM, 1e-5f);
    gemm_h<<<dim3(1, BS / 128), 256, GH_SMEM>>>(
        lnh, wh_head, head_b, nullptr, out, nullptr, BS, NC, HDIM, 0);
}

// round 8
// speedup vs baseline: 6.4754x; 1.1588x over previous
#include <cuda_runtime.h>
#include <cuda_fp16.h>
#include <math.h>
#include <stdint.h>

// ---------------------------------------------------------------------------
// CausalTransformer: B=2, T=5120, FEAT=256, TIN=5 -> S=1024 patches
// HDIM=1024, N_HEADS=16, HEAD_DIM=64, N_LAYERS=8, FF_DIM=4096, NUM_CLASSES=100
// Round 8: fp16 flash attention (m16n8k16, hi/lo-compensated QK logits).
// ---------------------------------------------------------------------------

#define SLEN   1024
#define NB     2
#define BS     2048
#define HDIM   1024
#define INDIM  1280
#define QKVD   3072
#define FFD    4096
#define NH     16
#define HD     64
#define NC     100
#define NLAY   8
#define LREL   257

// ------------------------- scratch (device globals) ------------------------
__device__ float  g_z[(size_t)BS * HDIM];
__device__ float  g_qkv[(size_t)BS * QKVD];
__device__ float  g_ff[(size_t)BS * HDIM];
__device__ __half g_lnh[(size_t)BS * INDIM];
__device__ __half g_oh[(size_t)BS * HDIM];
__device__ __half g_ffh[(size_t)BS * FFD];
#define WOFF_PE   ((size_t)0)
#define WOFF_QKV  (WOFF_PE  + (size_t)INDIM * HDIM)
#define WOFF_OUT  (WOFF_QKV + (size_t)NLAY * QKVD * HDIM)
#define WOFF_FC1  (WOFF_OUT + (size_t)NLAY * HDIM * HDIM)
#define WOFF_FC2  (WOFF_FC1 + (size_t)NLAY * FFD * HDIM)
#define WOFF_HEAD (WOFF_FC2 + (size_t)NLAY * HDIM * FFD)
#define WTOTAL    (WOFF_HEAD + (size_t)NC * HDIM)
__device__ __half g_wh[WTOTAL];

// ---------------------------- helpers ---------------------------------------
__device__ __forceinline__ void mma_f16(float (&d)[4],
                                        const uint32_t (&a)[4],
                                        const uint32_t (&b)[2])
{
    asm volatile(
        "mma.sync.aligned.m16n8k16.row.col.f32.f16.f16.f32 "
        "{%0,%1,%2,%3}, {%4,%5,%6,%7}, {%8,%9}, {%0,%1,%2,%3};\n"
        : "+f"(d[0]), "+f"(d[1]), "+f"(d[2]), "+f"(d[3])
        : "r"(a[0]), "r"(a[1]), "r"(a[2]), "r"(a[3]),
          "r"(b[0]), "r"(b[1]));
}

__device__ __forceinline__ uint32_t smem_u32(const void* p)
{
    uint32_t a;
    asm("{ .reg .u64 t; cvta.to.shared.u64 t, %1; cvt.u32.u64 %0, t; }"
        : "=r"(a) : "l"(p));
    return a;
}

#define CP16(dst, src) \
    asm volatile("cp.async.cg.shared.global [%0], [%1], 16;" \
                 :: "r"(dst), "l"(src))

// split float into fp16 hi + fp16 lo, pack pairs into u32
__device__ __forceinline__ void hl_pack(float a, float b,
                                        uint32_t& hi, uint32_t& lo)
{
    __half ha = __float2half_rn(a), hb = __float2half_rn(b);
    __half la = __float2half_rn(a - __half2float(ha));
    __half lb = __float2half_rn(b - __half2float(hb));
    __half2 H = __halves2half2(ha, hb), L = __halves2half2(la, lb);
    hi = *(uint32_t*)&H;
    lo = *(uint32_t*)&L;
}

// --------------------------- weight fp16 conversion -------------------------
__global__ void cvt_h(const float* __restrict__ in, __half* __restrict__ out,
                      int n4)
{
    for (int i = blockIdx.x * blockDim.x + threadIdx.x; i < n4;
         i += gridDim.x * blockDim.x) {
        float4 v = ((const float4*)in)[i];
        __half2 h0 = __floats2half2_rn(v.x, v.y);
        __half2 h1 = __floats2half2_rn(v.z, v.w);
        uint2 u;
        u.x = *(uint32_t*)&h0;
        u.y = *(uint32_t*)&h1;
        ((uint2*)out)[i] = u;
    }
}

// --------------------------- LayerNorm (warp/row) ---------------------------
__global__ void ln_kernel(const float* __restrict__ in,
                          float* __restrict__ outF, __half* __restrict__ outH,
                          const float* __restrict__ g, const float* __restrict__ b,
                          int n, float eps)
{
    int w = threadIdx.x >> 5, lane = threadIdx.x & 31;
    int row = blockIdx.x * 8 + w;
    const float4* p4 = (const float4*)(in + (size_t)row * n);
    int n4 = n >> 2;

    float s = 0.f, ss = 0.f;
    for (int i = lane; i < n4; i += 32) {
        float4 v = p4[i];
        s  += v.x + v.y + v.z + v.w;
        ss += v.x * v.x + v.y * v.y + v.z * v.z + v.w * v.w;
    }
#pragma unroll
    for (int off = 16; off > 0; off >>= 1) {
        s  += __shfl_xor_sync(0xffffffffu, s, off);
        ss += __shfl_xor_sync(0xffffffffu, ss, off);
    }
    float mean = s / n;
    float var  = ss / n - mean * mean;
    float inv  = rsqrtf(var + eps);

    const float4* g4 = (const float4*)g;
    const float4* b4 = (const float4*)b;
    for (int i = lane; i < n4; i += 32) {
        float4 v = p4[i], gg = g4[i], bb = b4[i];
        v.x = (v.x - mean) * inv * gg.x + bb.x;
        v.y = (v.y - mean) * inv * gg.y + bb.y;
        v.z = (v.z - mean) * inv * gg.z + bb.z;
        v.w = (v.w - mean) * inv * gg.w + bb.w;
        if (outH) {
            __half2 h0 = __floats2half2_rn(v.x, v.y);
            __half2 h1 = __floats2half2_rn(v.z, v.w);
            uint2 u;
            u.x = *(uint32_t*)&h0;
            u.y = *(uint32_t*)&h1;
            *(uint2*)(outH + (size_t)row * n + i * 4) = u;
        } else {
            *(float4*)(outF + (size_t)row * n + i * 4) = v;
        }
    }
}

// -------- 3-stage cp.async fp16 GEMM: C = act(A W^T + b) + res --------------
#define BKH   32
#define SH    40
#define HSTAGE ((128 + 128) * SH)
#define GH_SMEM (3 * HSTAGE * 2)

__global__ void __launch_bounds__(256, 2)
gemm_h(const __half* __restrict__ A, const __half* __restrict__ W,
       const float* __restrict__ bias, const float* __restrict__ res,
       float* __restrict__ Cf, __half* __restrict__ Ch,
       int M, int N, int K, int act)
{
    extern __shared__ __half smh[];
    int t = threadIdx.x, lane = t & 31, wid = t >> 5;
    int wm = wid & 3, wn = wid >> 2;
    int m0 = blockIdx.y * 128, n0 = blockIdx.x * 128;
    int g = lane >> 2, tt = lane & 3;
    uint32_t sbase = smem_u32(smh);

    float acc[2][8][4];
#pragma unroll
    for (int mi = 0; mi < 2; mi++)
#pragma unroll
        for (int ni = 0; ni < 8; ni++)
#pragma unroll
            for (int c = 0; c < 4; c++) acc[mi][ni][c] = 0.f;

    int niter = K / BKH;

    auto stage = [&](int s, int k0) {
        uint32_t sb = sbase + 2 * s * HSTAGE;
#pragma unroll
        for (int u = 0; u < 4; u++) {
            int i   = t + u * 256;
            int row = (i >> 2) & 127;
            int seg = i & 3;
            int isB = i >> 9;
            uint32_t dst = sb + (uint32_t)(isB * (128 * SH * 2))
                         + (uint32_t)(row * (SH * 2) + seg * 16);
            const __half* src;
            if (isB) {
                int rw = n0 + row; if (rw >= N) rw = N - 1;
                src = W + (size_t)rw * K + k0 + seg * 8;
            } else {
                src = A + (size_t)(m0 + row) * K + k0 + seg * 8;
            }
            CP16(dst, src);
        }
        asm volatile("cp.async.commit_group;");
    };

    stage(0, 0);
    if (niter > 1) stage(1, BKH);
    int s = 0;
    for (int it = 0; it < niter; it++) {
        if (it + 1 < niter)
            asm volatile("cp.async.wait_group 1;");
        else
            asm volatile("cp.async.wait_group 0;");
        __syncthreads();

        const __half* As_ = smh + s * HSTAGE;
        const __half* Ws_ = As_ + 128 * SH;
#pragma unroll
        for (int ks = 0; ks < BKH; ks += 16) {
            uint32_t af[2][4], bf[8][2];
#pragma unroll
            for (int mi = 0; mi < 2; mi++) {
                int r0 = (wm * 32 + mi * 16 + g) * SH + ks + 2 * tt;
                af[mi][0] = *(const uint32_t*)&As_[r0];
                af[mi][1] = *(const uint32_t*)&As_[r0 + 8 * SH];
                af[mi][2] = *(const uint32_t*)&As_[r0 + 8];
                af[mi][3] = *(const uint32_t*)&As_[r0 + 8 * SH + 8];
            }
#pragma unroll
            for (int ni = 0; ni < 8; ni++) {
                int r0 = (wn * 64 + ni * 8 + g) * SH + ks + 2 * tt;
                bf[ni][0] = *(const uint32_t*)&Ws_[r0];
                bf[ni][1] = *(const uint32_t*)&Ws_[r0 + 8];
            }
#pragma unroll
            for (int mi = 0; mi < 2; mi++)
#pragma unroll
                for (int ni = 0; ni < 8; ni++)
                    mma_f16(acc[mi][ni], af[mi], bf[ni]);
        }

        if (it + 2 < niter) {
            int sn = s + 2; if (sn >= 3) sn -= 3;
            stage(sn, (it + 2) * BKH);
        }
        s = (s + 1 == 3) ? 0 : s + 1;
    }

#pragma unroll
    for (int mi = 0; mi < 2; mi++) {
#pragma unroll
        for (int ni = 0; ni < 8; ni++) {
            int m = m0 + wm * 32 + mi * 16 + g;
            int n = n0 + wn * 64 + ni * 8 + tt * 2;
            if (n >= N) continue;
            float bn0 = bias[n], bn1 = bias[n + 1];
#pragma unroll
            for (int r = 0; r < 2; r++) {
                int mm = m + r * 8;
                float v0 = acc[mi][ni][r * 2 + 0] + bn0;
                float v1 = acc[mi][ni][r * 2 + 1] + bn1;
                if (act == 1) {
                    v0 = 0.5f * v0 * (1.0f + erff(v0 * 0.70710678118654752f));
                    v1 = 0.5f * v1 * (1.0f + erff(v1 * 0.70710678118654752f));
                }
                if (res) {
                    const float2 rv = *(const float2*)(res + (size_t)mm * N + n);
                    v0 += rv.x; v1 += rv.y;
                }
                if (Ch) {
                    __half2 hh = __floats2half2_rn(v0, v1);
                    *(__half2*)(Ch + (size_t)mm * N + n) = hh;
                } else {
                    *(float2*)(Cf + (size_t)mm * N + n) = make_float2(v0, v1);
                }
            }
        }
    }
}

// ---------------------- fused flash attention (fp16) ------------------------
// 128 q-rows x head per block, 8 warps (16 rows each). QK logits via fp16
// hi/lo compensation (3 MMAs) -> fp32-accurate. PV single fp16.
// smem: rel 260f | Khi,Klo,Vp: u32[32][72] each | Ps: half[128][72]
#define KP2 72
#define PST 72
#define FA_SMEM_BYTES (260 * 4 + 3 * 32 * KP2 * 4 + 128 * PST * 2)

__global__ void __launch_bounds__(256, 1)
flash_kernel(const float* __restrict__ qkv, const float* __restrict__ rel,
             __half* __restrict__ o)
{
    extern __shared__ float sm[];
    float*    rel_s = sm;
    uint32_t* Khi = (uint32_t*)(sm + 260);
    uint32_t* Klo = Khi + 32 * KP2;
    uint32_t* Vp  = Klo + 32 * KP2;
    __half*   Ps  = (__half*)(Vp + 32 * KP2);

    int bh = blockIdx.y, b = bh >> 4, h = bh & 15;
    int qt = gridDim.x - 1 - blockIdx.x;      // heavy tiles first
    int q0 = qt * 128;
    int t = threadIdx.x, lane = t & 31, w = t >> 5;
    int g = lane >> 2, tt = lane & 3;

    for (int i = t; i < LREL; i += 256) rel_s[i] = rel[h * LREL + i];

    // ---- Q fragments (fp16 hi/lo) in registers, 4 k16-chunks ----
    uint32_t qh[4][4], ql[4][4];
    {
        const float* qp0 = qkv + (size_t)(b * SLEN + q0 + w * 16 + g) * QKVD + h * HD;
        const float* qp1 = qp0 + (size_t)8 * QKVD;
#pragma unroll
        for (int kc = 0; kc < 4; kc++) {
            int d0 = kc * 16 + 2 * tt;
            hl_pack(qp0[d0],     qp0[d0 + 1], qh[kc][0], ql[kc][0]);
            hl_pack(qp1[d0],     qp1[d0 + 1], qh[kc][1], ql[kc][1]);
            hl_pack(qp0[d0 + 8], qp0[d0 + 9], qh[kc][2], ql[kc][2]);
            hl_pack(qp1[d0 + 8], qp1[d0 + 9], qh[kc][3], ql[kc][3]);
        }
    }

    float oacc[8][4];
#pragma unroll
    for (int nt = 0; nt < 8; nt++)
#pragma unroll
        for (int c = 0; c < 4; c++) oacc[nt][c] = 0.f;
    float mrow0 = -1e30f, mrow1 = -1e30f;
    float lrow0 = 0.f, lrow1 = 0.f;

    int q_g0 = q0 + w * 16 + g;
    int q_g1 = q_g0 + 8;
    int qm   = w * 16 + g;

    int nkt = 2 * qt + 2;
    for (int kt = 0; kt < nkt; kt++) {
        int kk0 = kt * 64;

        // ---- stage K (hi/lo half2 d-pairs) ----
        {
            int kr = t >> 2;                 // key 0..63
            int dc = (t & 3) * 16;
            const float* kp = qkv + (size_t)(b * SLEN + kk0 + kr) * QKVD
                            + HDIM + h * HD + dc;
#pragma unroll
            for (int u = 0; u < 4; u++) {
                float4 k4 = *(const float4*)(kp + u * 4);
                int dp = (dc + u * 4) >> 1;  // d-pair index
                uint32_t hi0, lo0, hi1, lo1;
                hl_pack(k4.x, k4.y, hi0, lo0);
                hl_pack(k4.z, k4.w, hi1, lo1);
                Khi[(dp    ) * KP2 + kr] = hi0;
                Klo[(dp    ) * KP2 + kr] = lo0;
                Khi[(dp + 1) * KP2 + kr] = hi1;
                Klo[(dp + 1) * KP2 + kr] = lo1;
            }
        }
        // ---- stage V (half2 key-pairs) ----
        {
            int r   = t >> 3;                // key-pair 0..31
            int dc2 = (t & 7) * 8;
            const float* vp0 = qkv + (size_t)(b * SLEN + kk0 + 2 * r) * QKVD
                             + 2 * HDIM + h * HD + dc2;
            const float* vp1 = vp0 + QKVD;
            float4 a0 = *(const float4*)(vp0);
            float4 a1 = *(const float4*)(vp0 + 4);
            float4 b0 = *(const float4*)(vp1);
            float4 b1 = *(const float4*)(vp1 + 4);
            float va[8] = {a0.x, a0.y, a0.z, a0.w, a1.x, a1.y, a1.z, a1.w};
            float vb[8] = {b0.x, b0.y, b0.z, b0.w, b1.x, b1.y, b1.z, b1.w};
#pragma unroll
            for (int j = 0; j < 8; j++) {
                __half2 hv = __floats2half2_rn(va[j], vb[j]);
                Vp[r * KP2 + dc2 + j] = *(uint32_t*)&hv;
            }
        }
        __syncthreads();

        // ---- S = Q K^T (fp16 hi/lo, fp32-accurate logits) ----
        float sc[8][4];
#pragma unroll
        for (int nt = 0; nt < 8; nt++)
#pragma unroll
            for (int c = 0; c < 4; c++) sc[nt][c] = 0.f;

#pragma unroll
        for (int kc = 0; kc < 4; kc++) {
#pragma unroll
            for (int nt = 0; nt < 8; nt++) {
                uint32_t bh_[2], bl_[2];
                int i0 = (kc * 8 + tt) * KP2 + nt * 8 + g;
                int i1 = (kc * 8 + tt + 4) * KP2 + nt * 8 + g;
                bh_[0] = Khi[i0]; bh_[1] = Khi[i1];
                bl_[0] = Klo[i0]; bl_[1] = Klo[i1];
                mma_f16(sc[nt], qh[kc], bh_);
                mma_f16(sc[nt], qh[kc], bl_);
                mma_f16(sc[nt], ql[kc], bh_);
            }
        }

        // ---- bias + causal mask ----
#pragma unroll
        for (int nt = 0; nt < 8; nt++) {
            int k0c = kk0 + nt * 8 + 2 * tt;
#pragma unroll
            for (int j = 0; j < 2; j++) {
                int k = k0c + j;
                int r0 = min(max(k - q_g0, -128), 128) + 128;
                int r1 = min(max(k - q_g1, -128), 128) + 128;
                float s0 = sc[nt][j]     * 0.125f + rel_s[r0];
                float s1 = sc[nt][2 + j] * 0.125f + rel_s[r1];
                sc[nt][j]     = (k > q_g0) ? -1e9f : s0;
                sc[nt][2 + j] = (k > q_g1) ? -1e9f : s1;
            }
        }

        // ---- online softmax ----
        float mx0 = -1e30f, mx1 = -1e30f;
#pragma unroll
        for (int nt = 0; nt < 8; nt++) {
            mx0 = fmaxf(mx0, fmaxf(sc[nt][0], sc[nt][1]));
            mx1 = fmaxf(mx1, fmaxf(sc[nt][2], sc[nt][3]));
        }
        mx0 = fmaxf(mx0, __shfl_xor_sync(0xffffffffu, mx0, 1));
        mx0 = fmaxf(mx0, __shfl_xor_sync(0xffffffffu, mx0, 2));
        mx1 = fmaxf(mx1, __shfl_xor_sync(0xffffffffu, mx1, 1));
        mx1 = fmaxf(mx1, __shfl_xor_sync(0xffffffffu, mx1, 2));
        float mnew0 = fmaxf(mrow0, mx0);
        float mnew1 = fmaxf(mrow1, mx1);
        float scale0 = __expf(mrow0 - mnew0);
        float scale1 = __expf(mrow1 - mnew1);

        float sum0 = 0.f, sum1 = 0.f;
#pragma unroll
        for (int nt = 0; nt < 8; nt++) {
            float p0 = __expf(sc[nt][0] - mnew0);
            float p1 = __expf(sc[nt][1] - mnew0);
            float p2 = __expf(sc[nt][2] - mnew1);
            float p3 = __expf(sc[nt][3] - mnew1);
            sum0 += p0 + p1;
            sum1 += p2 + p3;
            int kc0 = nt * 8 + 2 * tt;
            __half2 P0 = __floats2half2_rn(p0, p1);
            __half2 P1 = __floats2half2_rn(p2, p3);
            *(__half2*)&Ps[(qm    ) * PST + kc0] = P0;
            *(__half2*)&Ps[(qm + 8) * PST + kc0] = P1;
        }
        sum0 += __shfl_xor_sync(0xffffffffu, sum0, 1);
        sum0 += __shfl_xor_sync(0xffffffffu, sum0, 2);
        sum1 += __shfl_xor_sync(0xffffffffu, sum1, 1);
        sum1 += __shfl_xor_sync(0xffffffffu, sum1, 2);

        lrow0 = lrow0 * scale0 + sum0;
        lrow1 = lrow1 * scale1 + sum1;
        mrow0 = mnew0; mrow1 = mnew1;
#pragma unroll
        for (int nt = 0; nt < 8; nt++) {
            oacc[nt][0] *= scale0; oacc[nt][1] *= scale0;
            oacc[nt][2] *= scale1; oacc[nt][3] *= scale1;
        }
        __syncwarp();

        // ---- O += P V  (fp16) ----
#pragma unroll
        for (int kc = 0; kc < 4; kc++) {
            uint32_t af[4];
            af[0] = *(const uint32_t*)&Ps[(qm    ) * PST + kc * 16 + 2 * tt];
            af[1] = *(const uint32_t*)&Ps[(qm + 8) * PST + kc * 16 + 2 * tt];
            af[2] = *(const uint32_t*)&Ps[(qm    ) * PST + kc * 16 + 2 * tt + 8];
            af[3] = *(const uint32_t*)&Ps[(qm + 8) * PST + kc * 16 + 2 * tt + 8];
#pragma unroll
            for (int nt = 0; nt < 8; nt++) {
                uint32_t bf[2];
                bf[0] = Vp[(kc * 8 + tt)     * KP2 + nt * 8 + g];
                bf[1] = Vp[(kc * 8 + tt + 4) * KP2 + nt * 8 + g];
                mma_f16(oacc[nt], af, bf);
            }
        }
        __syncthreads();
    }

    // ---- epilogue: O / l -> fp16 ----
    float inv0 = 1.0f / lrow0;
    float inv1 = 1.0f / lrow1;
    __half* op = o + (size_t)(b * SLEN + q_g0) * HDIM + h * HD;
#pragma unroll
    for (int nt = 0; nt < 8; nt++) {
        int d = nt * 8 + 2 * tt;
        *(__half2*)(op + d) =
            __floats2half2_rn(oacc[nt][0] * inv0, oacc[nt][1] * inv0);
        *(__half2*)(op + (size_t)8 * HDIM + d) =
            __floats2half2_rn(oacc[nt][2] * inv1, oacc[nt][3] * inv1);
    }
}

// ------------------------------- launcher -----------------------------------
extern "C" void kernel_launch(void* const* d_in, const int* in_sizes, int n_in,
                              void* d_out, int out_size)
{
    const float* x        = (const float*)d_in[0];
    const float* pe_ln1_g = (const float*)d_in[1];
    const float* pe_ln1_b = (const float*)d_in[2];
    const float* pe_w     = (const float*)d_in[3];
    const float* pe_b     = (const float*)d_in[4];
    const float* pe_ln2_g = (const float*)d_in[5];
    const float* pe_ln2_b = (const float*)d_in[6];
    const float* lnA_g    = (const float*)d_in[7];
    const float* lnA_b    = (const float*)d_in[8];
    const float* qkv_w    = (const float*)d_in[9];
    const float* qkv_b    = (const float*)d_in[10];
    const float* out_w    = (const float*)d_in[11];
    const float* out_b    = (const float*)d_in[12];
    const float* lnF_g    = (const float*)d_in[13];
    const float* lnF_b    = (const float*)d_in[14];
    const float* fc1_w    = (const float*)d_in[15];
    const float* fc1_b    = (const float*)d_in[16];
    const float* fc2_w    = (const float*)d_in[17];
    const float* fc2_b    = (const float*)d_in[18];
    const float* relt     = (const float*)d_in[19];
    const float* final_g  = (const float*)d_in[20];
    const float* final_b  = (const float*)d_in[21];
    const float* head_w   = (const float*)d_in[22];
    const float* head_b   = (const float*)d_in[23];
    float* out = (float*)d_out;

    float *z, *qkv, *ff;
    __half *lnh, *oh, *ffh, *wh;
    cudaGetSymbolAddress((void**)&z,   g_z);
    cudaGetSymbolAddress((void**)&qkv, g_qkv);
    cudaGetSymbolAddress((void**)&ff,  g_ff);
    cudaGetSymbolAddress((void**)&lnh, g_lnh);
    cudaGetSymbolAddress((void**)&oh,  g_oh);
    cudaGetSymbolAddress((void**)&ffh, g_ffh);
    cudaGetSymbolAddress((void**)&wh,  g_wh);

    cudaFuncSetAttribute(flash_kernel,
                         cudaFuncAttributeMaxDynamicSharedMemorySize,
                         FA_SMEM_BYTES);
    cudaFuncSetAttribute(gemm_h,
                         cudaFuncAttributeMaxDynamicSharedMemorySize,
                         GH_SMEM);

    __half* wh_pe   = wh + WOFF_PE;
    __half* wh_qkv  = wh + WOFF_QKV;
    __half* wh_out  = wh + WOFF_OUT;
    __half* wh_fc1  = wh + WOFF_FC1;
    __half* wh_fc2  = wh + WOFF_FC2;
    __half* wh_head = wh + WOFF_HEAD;

    // ---- convert all weights to fp16 (rn) ----
    cvt_h<<<2048, 256>>>(pe_w,   wh_pe,   (int)((size_t)INDIM * HDIM / 4));
    cvt_h<<<2048, 256>>>(qkv_w,  wh_qkv,  (int)((size_t)NLAY * QKVD * HDIM / 4));
    cvt_h<<<2048, 256>>>(out_w,  wh_out,  (int)((size_t)NLAY * HDIM * HDIM / 4));
    cvt_h<<<2048, 256>>>(fc1_w,  wh_fc1,  (int)((size_t)NLAY * FFD * HDIM / 4));
    cvt_h<<<2048, 256>>>(fc2_w,  wh_fc2,  (int)((size_t)NLAY * HDIM * FFD / 4));
    cvt_h<<<2048, 256>>>(head_w, wh_head, (int)((size_t)NC * HDIM / 4));

    // ---- patch embed ----
    ln_kernel<<<BS / 8, 256>>>(x, nullptr, lnh, pe_ln1_g, pe_ln1_b, INDIM, 1e-6f);
    gemm_h<<<dim3(HDIM / 128, BS / 128), 256, GH_SMEM>>>(
        lnh, wh_pe, pe_b, nullptr, ff, nullptr, BS, HDIM, INDIM, 0);
    ln_kernel<<<BS / 8, 256>>>(ff, z, nullptr, pe_ln2_g, pe_ln2_b, HDIM, 1e-6f);

    // ---- transformer layers ----
    for (int l = 0; l < NLAY; l++) {
        ln_kernel<<<BS / 8, 256>>>(z, nullptr, lnh, lnA_g + (size_t)l * HDIM,
                                   lnA_b + (size_t)l * HDIM, HDIM, 1e-5f);
        gemm_h<<<dim3(QKVD / 128, BS / 128), 256, GH_SMEM>>>(
            lnh, wh_qkv + (size_t)l * QKVD * HDIM, qkv_b + (size_t)l * QKVD,
            nullptr, qkv, nullptr, BS, QKVD, HDIM, 0);

        flash_kernel<<<dim3(8, NB * NH), 256, FA_SMEM_BYTES>>>(qkv, relt, oh);

        gemm_h<<<dim3(HDIM / 128, BS / 128), 256, GH_SMEM>>>(
            oh, wh_out + (size_t)l * HDIM * HDIM, out_b + (size_t)l * HDIM,
            z, z, nullptr, BS, HDIM, HDIM, 0);

        ln_kernel<<<BS / 8, 256>>>(z, nullptr, lnh, lnF_g + (size_t)l * HDIM,
                                   lnF_b + (size_t)l * HDIM, HDIM, 1e-5f);
        gemm_h<<<dim3(FFD / 128, BS / 128), 256, GH_SMEM>>>(
            lnh, wh_fc1 + (size_t)l * FFD * HDIM, fc1_b + (size_t)l * FFD,
            nullptr, nullptr, ffh, BS, FFD, HDIM, 1);
        gemm_h<<<dim3(HDIM / 128, BS / 128), 256, GH_SMEM>>>(
            ffh, wh_fc2 + (size_t)l * HDIM * FFD, fc2_b + (size_t)l * HDIM,
            z, z, nullptr, BS, HDIM, FFD, 0);
    }

    // ---- head ----
    ln_kernel<<<BS / 8, 256>>>(z, nullptr, lnh, final_g, final_b, HDIM, 1e-5f);
    gemm_h<<<dim3(1, BS / 128), 256, GH_SMEM>>>(
        lnh, wh_head, head_b, nullptr, out, nullptr, BS, NC, HDIM, 0);
}